// round 2
// baseline (speedup 1.0000x reference)
#include <cuda_runtime.h>
#include <cuda_bf16.h>
#include <cstdint>

// ---------------------------------------------------------------------------
// LEFTNet message-passing layer, fp32 baseline.
//   xh   = silu(x@xw1+xb1)@xw2+xb2                      [N,384]
//   rbfh = rbf@rw+rb                                    [E,384]
//   w    = silu(weight@iw1+ib1)@iw2+ib2                 [E,384]
//   m    = xh[src] * rbfh * w                           [E,384]
//   xm, xh2, xh3 = split(m);  xh2 *= 1/sqrt(3)
//   vecm = (vec[src]*xh2 + xh3*edge_vector) / sqrt(128) [E,3,128]
//   dx   = segsum(xm, dst);  dvec = segsum(vecm, dst)
// ---------------------------------------------------------------------------

#define NN_MAX 50000
#define NE_MAX 500000

__device__ float g_h1[(size_t)NN_MAX * 128];   // silu(x@xw1+b)
__device__ float g_xh[(size_t)NN_MAX * 384];   // node projection
__device__ float g_t1[(size_t)NE_MAX * 384];   // silu(weight@iw1+b)
__device__ float g_m [(size_t)NE_MAX * 384];   // rbfh, then final message m

// ---------------------------------------------------------------------------
// Generic tiled SGEMM:  C = act(A[M,K] @ B[K,N] + bias[N])
// BM=BN=128, BK=16, 256 threads, 8x8 split micro-tile per thread.
// Requires: K % 16 == 0, N % 128 == 0. M is bounds-checked.
// ---------------------------------------------------------------------------
#define BM 128
#define BN 128
#define BK 16

__device__ __forceinline__ float silu_f(float v) {
    return v * (1.0f / (1.0f + __expf(-v)));
}

template<bool SILU>
__global__ __launch_bounds__(256, 2)
void sgemm_bias_act(const float* __restrict__ A, const float* __restrict__ B,
                    const float* __restrict__ bias, float* __restrict__ C,
                    int M, int N, int K)
{
    __shared__ float As[BK][BM + 4];
    __shared__ float Bs[BK][BN];

    const int tid  = threadIdx.x;
    const int tx   = tid & 15;
    const int ty   = tid >> 4;
    const int row0 = blockIdx.y * BM;
    const int col0 = blockIdx.x * BN;

    float acc[8][8];
#pragma unroll
    for (int i = 0; i < 8; i++)
#pragma unroll
        for (int j = 0; j < 8; j++) acc[i][j] = 0.0f;

    const int a_row = tid >> 2;          // 0..63
    const int a_seg = tid & 3;           // k sub-offset (0..3)*4
    const int b_kk  = tid >> 5;          // 0..7
    const int b_c4  = (tid & 31) << 2;   // 0..124

    for (int k0 = 0; k0 < K; k0 += BK) {
#pragma unroll
        for (int it = 0; it < 2; it++) {
            int r  = a_row + it * 64;
            int gr = row0 + r;
            float4 v = make_float4(0.f, 0.f, 0.f, 0.f);
            if (gr < M)
                v = *(const float4*)&A[(size_t)gr * K + k0 + a_seg * 4];
            As[a_seg * 4 + 0][r] = v.x;
            As[a_seg * 4 + 1][r] = v.y;
            As[a_seg * 4 + 2][r] = v.z;
            As[a_seg * 4 + 3][r] = v.w;
        }
#pragma unroll
        for (int it = 0; it < 2; it++) {
            int kk = b_kk + it * 8;
            *(float4*)&Bs[kk][b_c4] =
                *(const float4*)&B[(size_t)(k0 + kk) * N + col0 + b_c4];
        }
        __syncthreads();

#pragma unroll
        for (int kk = 0; kk < BK; kk++) {
            float4 a0 = *(const float4*)&As[kk][ty * 4];
            float4 a1 = *(const float4*)&As[kk][64 + ty * 4];
            float4 b0 = *(const float4*)&Bs[kk][tx * 4];
            float4 b1 = *(const float4*)&Bs[kk][64 + tx * 4];
            float a[8] = {a0.x, a0.y, a0.z, a0.w, a1.x, a1.y, a1.z, a1.w};
            float b[8] = {b0.x, b0.y, b0.z, b0.w, b1.x, b1.y, b1.z, b1.w};
#pragma unroll
            for (int i = 0; i < 8; i++)
#pragma unroll
                for (int j = 0; j < 8; j++)
                    acc[i][j] += a[i] * b[j];
        }
        __syncthreads();
    }

#pragma unroll
    for (int i = 0; i < 8; i++) {
        int r  = (i < 4) ? (ty * 4 + i) : (64 + ty * 4 + (i - 4));
        int gr = row0 + r;
        if (gr >= M) continue;
#pragma unroll
        for (int jg = 0; jg < 2; jg++) {
            int c  = (jg == 0) ? (tx * 4) : (64 + tx * 4);
            int gc = col0 + c;
            float4 bi = *(const float4*)&bias[gc];
            float4 o;
            o.x = acc[i][jg * 4 + 0] + bi.x;
            o.y = acc[i][jg * 4 + 1] + bi.y;
            o.z = acc[i][jg * 4 + 2] + bi.z;
            o.w = acc[i][jg * 4 + 3] + bi.w;
            if (SILU) {
                o.x = silu_f(o.x); o.y = silu_f(o.y);
                o.z = silu_f(o.z); o.w = silu_f(o.w);
            }
            *(float4*)&C[(size_t)gr * N + gc] = o;
        }
    }
}

// ---------------------------------------------------------------------------
// GEMM3 fused:  Cm[gr,gc] = (A@B + ib2)[gr,gc] * Cm[gr,gc] * xh[src[gr], gc]
// A = g_t1 [E,384], B = iw2 [384,384]. Cm holds rbfh on input, message m out.
// ---------------------------------------------------------------------------
__global__ __launch_bounds__(256, 2)
void gemm3_fused(const float* __restrict__ A, const float* __restrict__ B,
                 const float* __restrict__ bias, float* __restrict__ Cm,
                 const float* __restrict__ xh, const int* __restrict__ src,
                 int M)
{
    const int N = 384, K = 384;
    __shared__ float As[BK][BM + 4];
    __shared__ float Bs[BK][BN];

    const int tid  = threadIdx.x;
    const int tx   = tid & 15;
    const int ty   = tid >> 4;
    const int row0 = blockIdx.y * BM;
    const int col0 = blockIdx.x * BN;

    float acc[8][8];
#pragma unroll
    for (int i = 0; i < 8; i++)
#pragma unroll
        for (int j = 0; j < 8; j++) acc[i][j] = 0.0f;

    const int a_row = tid >> 2;
    const int a_seg = tid & 3;
    const int b_kk  = tid >> 5;
    const int b_c4  = (tid & 31) << 2;

    for (int k0 = 0; k0 < K; k0 += BK) {
#pragma unroll
        for (int it = 0; it < 2; it++) {
            int r  = a_row + it * 64;
            int gr = row0 + r;
            float4 v = make_float4(0.f, 0.f, 0.f, 0.f);
            if (gr < M)
                v = *(const float4*)&A[(size_t)gr * K + k0 + a_seg * 4];
            As[a_seg * 4 + 0][r] = v.x;
            As[a_seg * 4 + 1][r] = v.y;
            As[a_seg * 4 + 2][r] = v.z;
            As[a_seg * 4 + 3][r] = v.w;
        }
#pragma unroll
        for (int it = 0; it < 2; it++) {
            int kk = b_kk + it * 8;
            *(float4*)&Bs[kk][b_c4] =
                *(const float4*)&B[(size_t)(k0 + kk) * N + col0 + b_c4];
        }
        __syncthreads();

#pragma unroll
        for (int kk = 0; kk < BK; kk++) {
            float4 a0 = *(const float4*)&As[kk][ty * 4];
            float4 a1 = *(const float4*)&As[kk][64 + ty * 4];
            float4 b0 = *(const float4*)&Bs[kk][tx * 4];
            float4 b1 = *(const float4*)&Bs[kk][64 + tx * 4];
            float a[8] = {a0.x, a0.y, a0.z, a0.w, a1.x, a1.y, a1.z, a1.w};
            float b[8] = {b0.x, b0.y, b0.z, b0.w, b1.x, b1.y, b1.z, b1.w};
#pragma unroll
            for (int i = 0; i < 8; i++)
#pragma unroll
                for (int j = 0; j < 8; j++)
                    acc[i][j] += a[i] * b[j];
        }
        __syncthreads();
    }

#pragma unroll
    for (int i = 0; i < 8; i++) {
        int r  = (i < 4) ? (ty * 4 + i) : (64 + ty * 4 + (i - 4));
        int gr = row0 + r;
        if (gr >= M) continue;
        int s = src[gr];
#pragma unroll
        for (int jg = 0; jg < 2; jg++) {
            int c  = (jg == 0) ? (tx * 4) : (64 + tx * 4);
            int gc = col0 + c;
            float4 bi = *(const float4*)&bias[gc];
            float4 xv = *(const float4*)&xh[(size_t)s * 384 + gc];
            float4 rv = *(const float4*)&Cm[(size_t)gr * 384 + gc];
            float4 o;
            o.x = (acc[i][jg * 4 + 0] + bi.x) * rv.x * xv.x;
            o.y = (acc[i][jg * 4 + 1] + bi.y) * rv.y * xv.y;
            o.z = (acc[i][jg * 4 + 2] + bi.z) * rv.z * xv.z;
            o.w = (acc[i][jg * 4 + 3] + bi.w) * rv.w * xv.w;
            *(float4*)&Cm[(size_t)gr * 384 + gc] = o;
        }
    }
}

// ---------------------------------------------------------------------------
// Scatter: one warp per edge. Vector reductions into dx / dvec.
// ---------------------------------------------------------------------------
__device__ __forceinline__ void red_add_v4(float* p, float4 v) {
    asm volatile("red.global.add.v4.f32 [%0], {%1, %2, %3, %4};"
                 :: "l"(p), "f"(v.x), "f"(v.y), "f"(v.z), "f"(v.w)
                 : "memory");
}

__global__ void scatter_kernel(const float* __restrict__ m,
                               const float* __restrict__ vec,
                               const int*   __restrict__ ei,
                               const float* __restrict__ ev,
                               float* __restrict__ dx,
                               float* __restrict__ dvec,
                               int E)
{
    int gtid = blockIdx.x * blockDim.x + threadIdx.x;
    int e    = gtid >> 5;
    int lane = gtid & 31;
    if (e >= E) return;

    int s = ei[e];
    int d = ei[E + e];

    const float4* m4 = (const float4*)(m + (size_t)e * 384);
    float4 xm = m4[lane];
    float4 h2 = m4[32 + lane];
    float4 h3 = m4[64 + lane];

    const float is3 = 0.57735026918962576f;   // 1/sqrt(3)
    const float ish = 0.08838834764831845f;   // 1/sqrt(128)
    h2.x *= is3; h2.y *= is3; h2.z *= is3; h2.w *= is3;

    float evd[3];
    evd[0] = ev[(size_t)e * 3 + 0];
    evd[1] = ev[(size_t)e * 3 + 1];
    evd[2] = ev[(size_t)e * 3 + 2];

    red_add_v4(dx + (size_t)d * 128 + lane * 4, xm);

    const float4* v4 = (const float4*)(vec + (size_t)s * 384);
#pragma unroll
    for (int t = 0; t < 3; t++) {
        float4 v = v4[t * 32 + lane];
        float4 o;
        o.x = (v.x * h2.x + h3.x * evd[t]) * ish;
        o.y = (v.y * h2.y + h3.y * evd[t]) * ish;
        o.z = (v.z * h2.z + h3.z * evd[t]) * ish;
        o.w = (v.w * h2.w + h3.w * evd[t]) * ish;
        red_add_v4(dvec + ((size_t)d * 3 + t) * 128 + lane * 4, o);
    }
}

// ---------------------------------------------------------------------------
// Launch
// ---------------------------------------------------------------------------
extern "C" void kernel_launch(void* const* d_in, const int* in_sizes, int n_in,
                              void* d_out, int out_size)
{
    const float* x    = (const float*)d_in[0];
    const float* vec  = (const float*)d_in[1];
    const int*   ei   = (const int*)  d_in[2];
    const float* rbf  = (const float*)d_in[3];
    const float* wgt  = (const float*)d_in[4];
    const float* ev   = (const float*)d_in[5];
    const float* xw1  = (const float*)d_in[6];
    const float* xb1  = (const float*)d_in[7];
    const float* xw2  = (const float*)d_in[8];
    const float* xb2  = (const float*)d_in[9];
    const float* rw   = (const float*)d_in[10];
    const float* rb   = (const float*)d_in[11];
    const float* iw1  = (const float*)d_in[12];
    const float* ib1  = (const float*)d_in[13];
    const float* iw2  = (const float*)d_in[14];
    const float* ib2  = (const float*)d_in[15];

    const int nn = in_sizes[0] / 128;   // 50000 nodes
    const int ne = in_sizes[2] / 2;     // 500000 edges

    float* out  = (float*)d_out;
    float* dx   = out;
    float* dvec = out + (size_t)nn * 128;

    float *p_h1, *p_xh, *p_t1, *p_m;
    cudaGetSymbolAddress((void**)&p_h1, g_h1);
    cudaGetSymbolAddress((void**)&p_xh, g_xh);
    cudaGetSymbolAddress((void**)&p_t1, g_t1);
    cudaGetSymbolAddress((void**)&p_m,  g_m);

    cudaMemsetAsync(d_out, 0, (size_t)out_size * sizeof(float));

    dim3 blk(256);
    // node projection
    sgemm_bias_act<true ><<<dim3(1, (nn + BM - 1) / BM), blk>>>(x,    xw1, xb1, p_h1, nn, 128, 128);
    sgemm_bias_act<false><<<dim3(3, (nn + BM - 1) / BM), blk>>>(p_h1, xw2, xb2, p_xh, nn, 384, 128);
    // edge radial filter: g_m = rbf@rw + rb
    sgemm_bias_act<false><<<dim3(3, (ne + BM - 1) / BM), blk>>>(rbf,  rw,  rb,  p_m,  ne, 384, 32);
    // edge inv projection layer 1: g_t1 = silu(weight@iw1 + ib1)
    sgemm_bias_act<true ><<<dim3(3, (ne + BM - 1) / BM), blk>>>(wgt,  iw1, ib1, p_t1, ne, 384, 416);
    // layer 2 fused with rbfh and xh[src] gather: g_m = (g_t1@iw2+ib2)*g_m*xh[src]
    gemm3_fused<<<dim3(3, (ne + BM - 1) / BM), blk>>>(p_t1, iw2, ib2, p_m, p_xh, ei, ne);
    // message build + segment sum
    scatter_kernel<<<((size_t)ne * 32 + 255) / 256, 256>>>(p_m, vec, ei, ev, dx, dvec, ne);
}

// round 3
// speedup vs baseline: 1.1182x; 1.1182x over previous
#include <cuda_runtime.h>
#include <cuda_bf16.h>
#include <cstdint>

// ---------------------------------------------------------------------------
// LEFTNet message-passing layer. fp32 with packed FFMA2 (fma.rn.f32x2) GEMMs.
// ---------------------------------------------------------------------------

#define NN_MAX 50000
#define NE_MAX 500000

__device__ float g_h1[(size_t)NN_MAX * 128];   // silu(x@xw1+b)
__device__ float g_xh[(size_t)NN_MAX * 384];   // node projection
__device__ float g_t1[(size_t)NE_MAX * 384];   // silu(weight@iw1+b)
__device__ float g_m [(size_t)NE_MAX * 384];   // rbfh, then final message m

#define BM 128
#define BN 128
#define BK 16

__device__ __forceinline__ float silu_f(float v) {
    return v * (1.0f / (1.0f + __expf(-v)));
}

// ---- packed f32x2 helpers (Blackwell sm_100+) ------------------------------
__device__ __forceinline__ unsigned long long pack2(float lo, float hi) {
    unsigned long long r;
    asm("mov.b64 %0, {%1, %2};" : "=l"(r) : "f"(lo), "f"(hi));
    return r;
}
__device__ __forceinline__ void unpack2(unsigned long long v, float& lo, float& hi) {
    asm("mov.b64 {%0, %1}, %2;" : "=f"(lo), "=f"(hi) : "l"(v));
}
__device__ __forceinline__ void ffma2(unsigned long long& d,
                                      unsigned long long a,
                                      unsigned long long b) {
    asm("fma.rn.f32x2 %0, %1, %2, %0;" : "+l"(d) : "l"(a), "l"(b));
}

// ---------------------------------------------------------------------------
// Tiled SGEMM with FFMA2 inner loop:  C = act(A[M,K] @ B[K,N] + bias[N])
// BM=BN=128, BK=16, 256 threads, 8x8 micro-tile held as 8x4 f32x2 pairs.
// Requires: K % 16 == 0, N % 128 == 0. M bounds-checked.
// ---------------------------------------------------------------------------
template<bool SILU>
__global__ __launch_bounds__(256, 2)
void sgemm_bias_act(const float* __restrict__ A, const float* __restrict__ B,
                    const float* __restrict__ bias, float* __restrict__ C,
                    int M, int N, int K)
{
    __shared__ float As[BK][BM + 4];
    __shared__ float Bs[BK][BN];

    const int tid  = threadIdx.x;
    const int tx   = tid & 15;
    const int ty   = tid >> 4;
    const int row0 = blockIdx.y * BM;
    const int col0 = blockIdx.x * BN;

    unsigned long long acc2[8][4];
#pragma unroll
    for (int i = 0; i < 8; i++)
#pragma unroll
        for (int j = 0; j < 4; j++) acc2[i][j] = 0ull;

    const int a_row = tid >> 2;          // 0..63
    const int a_seg = tid & 3;           // k sub-offset (0..3)*4
    const int b_kk  = tid >> 5;          // 0..7
    const int b_c4  = (tid & 31) << 2;   // 0..124

    for (int k0 = 0; k0 < K; k0 += BK) {
#pragma unroll
        for (int it = 0; it < 2; it++) {
            int r  = a_row + it * 64;
            int gr = row0 + r;
            float4 v = make_float4(0.f, 0.f, 0.f, 0.f);
            if (gr < M)
                v = *(const float4*)&A[(size_t)gr * K + k0 + a_seg * 4];
            As[a_seg * 4 + 0][r] = v.x;
            As[a_seg * 4 + 1][r] = v.y;
            As[a_seg * 4 + 2][r] = v.z;
            As[a_seg * 4 + 3][r] = v.w;
        }
#pragma unroll
        for (int it = 0; it < 2; it++) {
            int kk = b_kk + it * 8;
            *(float4*)&Bs[kk][b_c4] =
                *(const float4*)&B[(size_t)(k0 + kk) * N + col0 + b_c4];
        }
        __syncthreads();

#pragma unroll
        for (int kk = 0; kk < BK; kk++) {
            float4 a0 = *(const float4*)&As[kk][ty * 4];
            float4 a1 = *(const float4*)&As[kk][64 + ty * 4];
            float4 b0 = *(const float4*)&Bs[kk][tx * 4];
            float4 b1 = *(const float4*)&Bs[kk][64 + tx * 4];
            unsigned long long bp[4] = {
                pack2(b0.x, b0.y), pack2(b0.z, b0.w),
                pack2(b1.x, b1.y), pack2(b1.z, b1.w)
            };
            float av[8] = {a0.x, a0.y, a0.z, a0.w, a1.x, a1.y, a1.z, a1.w};
#pragma unroll
            for (int i = 0; i < 8; i++) {
                unsigned long long ap = pack2(av[i], av[i]);
#pragma unroll
                for (int jp = 0; jp < 4; jp++)
                    ffma2(acc2[i][jp], ap, bp[jp]);
            }
        }
        __syncthreads();
    }

#pragma unroll
    for (int i = 0; i < 8; i++) {
        int r  = (i < 4) ? (ty * 4 + i) : (64 + ty * 4 + (i - 4));
        int gr = row0 + r;
        if (gr >= M) continue;
#pragma unroll
        for (int jg = 0; jg < 2; jg++) {
            int c  = (jg == 0) ? (tx * 4) : (64 + tx * 4);
            int gc = col0 + c;
            float4 bi = *(const float4*)&bias[gc];
            float4 o;
            unpack2(acc2[i][jg * 2 + 0], o.x, o.y);
            unpack2(acc2[i][jg * 2 + 1], o.z, o.w);
            o.x += bi.x; o.y += bi.y; o.z += bi.z; o.w += bi.w;
            if (SILU) {
                o.x = silu_f(o.x); o.y = silu_f(o.y);
                o.z = silu_f(o.z); o.w = silu_f(o.w);
            }
            *(float4*)&C[(size_t)gr * N + gc] = o;
        }
    }
}

// ---------------------------------------------------------------------------
// GEMM3 fused:  Cm[gr,gc] = (A@B + ib2)[gr,gc] * Cm[gr,gc] * xh[src[gr], gc]
// ---------------------------------------------------------------------------
__global__ __launch_bounds__(256, 2)
void gemm3_fused(const float* __restrict__ A, const float* __restrict__ B,
                 const float* __restrict__ bias, float* __restrict__ Cm,
                 const float* __restrict__ xh, const int* __restrict__ src,
                 int M)
{
    const int N = 384, K = 384;
    __shared__ float As[BK][BM + 4];
    __shared__ float Bs[BK][BN];

    const int tid  = threadIdx.x;
    const int tx   = tid & 15;
    const int ty   = tid >> 4;
    const int row0 = blockIdx.y * BM;
    const int col0 = blockIdx.x * BN;

    unsigned long long acc2[8][4];
#pragma unroll
    for (int i = 0; i < 8; i++)
#pragma unroll
        for (int j = 0; j < 4; j++) acc2[i][j] = 0ull;

    const int a_row = tid >> 2;
    const int a_seg = tid & 3;
    const int b_kk  = tid >> 5;
    const int b_c4  = (tid & 31) << 2;

    for (int k0 = 0; k0 < K; k0 += BK) {
#pragma unroll
        for (int it = 0; it < 2; it++) {
            int r  = a_row + it * 64;
            int gr = row0 + r;
            float4 v = make_float4(0.f, 0.f, 0.f, 0.f);
            if (gr < M)
                v = *(const float4*)&A[(size_t)gr * K + k0 + a_seg * 4];
            As[a_seg * 4 + 0][r] = v.x;
            As[a_seg * 4 + 1][r] = v.y;
            As[a_seg * 4 + 2][r] = v.z;
            As[a_seg * 4 + 3][r] = v.w;
        }
#pragma unroll
        for (int it = 0; it < 2; it++) {
            int kk = b_kk + it * 8;
            *(float4*)&Bs[kk][b_c4] =
                *(const float4*)&B[(size_t)(k0 + kk) * N + col0 + b_c4];
        }
        __syncthreads();

#pragma unroll
        for (int kk = 0; kk < BK; kk++) {
            float4 a0 = *(const float4*)&As[kk][ty * 4];
            float4 a1 = *(const float4*)&As[kk][64 + ty * 4];
            float4 b0 = *(const float4*)&Bs[kk][tx * 4];
            float4 b1 = *(const float4*)&Bs[kk][64 + tx * 4];
            unsigned long long bp[4] = {
                pack2(b0.x, b0.y), pack2(b0.z, b0.w),
                pack2(b1.x, b1.y), pack2(b1.z, b1.w)
            };
            float av[8] = {a0.x, a0.y, a0.z, a0.w, a1.x, a1.y, a1.z, a1.w};
#pragma unroll
            for (int i = 0; i < 8; i++) {
                unsigned long long ap = pack2(av[i], av[i]);
#pragma unroll
                for (int jp = 0; jp < 4; jp++)
                    ffma2(acc2[i][jp], ap, bp[jp]);
            }
        }
        __syncthreads();
    }

#pragma unroll
    for (int i = 0; i < 8; i++) {
        int r  = (i < 4) ? (ty * 4 + i) : (64 + ty * 4 + (i - 4));
        int gr = row0 + r;
        if (gr >= M) continue;
        int s = src[gr];
#pragma unroll
        for (int jg = 0; jg < 2; jg++) {
            int c  = (jg == 0) ? (tx * 4) : (64 + tx * 4);
            int gc = col0 + c;
            float4 bi = *(const float4*)&bias[gc];
            float4 xv = *(const float4*)&xh[(size_t)s * 384 + gc];
            float4 rv = *(const float4*)&Cm[(size_t)gr * 384 + gc];
            float4 o;
            unpack2(acc2[i][jg * 2 + 0], o.x, o.y);
            unpack2(acc2[i][jg * 2 + 1], o.z, o.w);
            o.x = (o.x + bi.x) * rv.x * xv.x;
            o.y = (o.y + bi.y) * rv.y * xv.y;
            o.z = (o.z + bi.z) * rv.z * xv.z;
            o.w = (o.w + bi.w) * rv.w * xv.w;
            *(float4*)&Cm[(size_t)gr * 384 + gc] = o;
        }
    }
}

// ---------------------------------------------------------------------------
// Scatter: one warp per edge. Vector reductions into dx / dvec.
// ---------------------------------------------------------------------------
__device__ __forceinline__ void red_add_v4(float* p, float4 v) {
    asm volatile("red.global.add.v4.f32 [%0], {%1, %2, %3, %4};"
                 :: "l"(p), "f"(v.x), "f"(v.y), "f"(v.z), "f"(v.w)
                 : "memory");
}

__global__ void scatter_kernel(const float* __restrict__ m,
                               const float* __restrict__ vec,
                               const int*   __restrict__ ei,
                               const float* __restrict__ ev,
                               float* __restrict__ dx,
                               float* __restrict__ dvec,
                               int E)
{
    int gtid = blockIdx.x * blockDim.x + threadIdx.x;
    int e    = gtid >> 5;
    int lane = gtid & 31;
    if (e >= E) return;

    int s = ei[e];
    int d = ei[E + e];

    const float4* m4 = (const float4*)(m + (size_t)e * 384);
    float4 xm = m4[lane];
    float4 h2 = m4[32 + lane];
    float4 h3 = m4[64 + lane];

    const float is3 = 0.57735026918962576f;   // 1/sqrt(3)
    const float ish = 0.08838834764831845f;   // 1/sqrt(128)
    h2.x *= is3; h2.y *= is3; h2.z *= is3; h2.w *= is3;

    float evd[3];
    evd[0] = ev[(size_t)e * 3 + 0];
    evd[1] = ev[(size_t)e * 3 + 1];
    evd[2] = ev[(size_t)e * 3 + 2];

    red_add_v4(dx + (size_t)d * 128 + lane * 4, xm);

    const float4* v4 = (const float4*)(vec + (size_t)s * 384);
#pragma unroll
    for (int t = 0; t < 3; t++) {
        float4 v = v4[t * 32 + lane];
        float4 o;
        o.x = (v.x * h2.x + h3.x * evd[t]) * ish;
        o.y = (v.y * h2.y + h3.y * evd[t]) * ish;
        o.z = (v.z * h2.z + h3.z * evd[t]) * ish;
        o.w = (v.w * h2.w + h3.w * evd[t]) * ish;
        red_add_v4(dvec + ((size_t)d * 3 + t) * 128 + lane * 4, o);
    }
}

// ---------------------------------------------------------------------------
// Launch
// ---------------------------------------------------------------------------
extern "C" void kernel_launch(void* const* d_in, const int* in_sizes, int n_in,
                              void* d_out, int out_size)
{
    const float* x    = (const float*)d_in[0];
    const float* vec  = (const float*)d_in[1];
    const int*   ei   = (const int*)  d_in[2];
    const float* rbf  = (const float*)d_in[3];
    const float* wgt  = (const float*)d_in[4];
    const float* ev   = (const float*)d_in[5];
    const float* xw1  = (const float*)d_in[6];
    const float* xb1  = (const float*)d_in[7];
    const float* xw2  = (const float*)d_in[8];
    const float* xb2  = (const float*)d_in[9];
    const float* rw   = (const float*)d_in[10];
    const float* rb   = (const float*)d_in[11];
    const float* iw1  = (const float*)d_in[12];
    const float* ib1  = (const float*)d_in[13];
    const float* iw2  = (const float*)d_in[14];
    const float* ib2  = (const float*)d_in[15];

    const int nn = in_sizes[0] / 128;   // 50000 nodes
    const int ne = in_sizes[2] / 2;     // 500000 edges

    float* out  = (float*)d_out;
    float* dx   = out;
    float* dvec = out + (size_t)nn * 128;

    float *p_h1, *p_xh, *p_t1, *p_m;
    cudaGetSymbolAddress((void**)&p_h1, g_h1);
    cudaGetSymbolAddress((void**)&p_xh, g_xh);
    cudaGetSymbolAddress((void**)&p_t1, g_t1);
    cudaGetSymbolAddress((void**)&p_m,  g_m);

    cudaMemsetAsync(d_out, 0, (size_t)out_size * sizeof(float));

    dim3 blk(256);
    // node projection
    sgemm_bias_act<true ><<<dim3(1, (nn + BM - 1) / BM), blk>>>(x,    xw1, xb1, p_h1, nn, 128, 128);
    sgemm_bias_act<false><<<dim3(3, (nn + BM - 1) / BM), blk>>>(p_h1, xw2, xb2, p_xh, nn, 384, 128);
    // edge radial filter: g_m = rbf@rw + rb
    sgemm_bias_act<false><<<dim3(3, (ne + BM - 1) / BM), blk>>>(rbf,  rw,  rb,  p_m,  ne, 384, 32);
    // edge inv projection layer 1: g_t1 = silu(weight@iw1 + ib1)
    sgemm_bias_act<true ><<<dim3(3, (ne + BM - 1) / BM), blk>>>(wgt,  iw1, ib1, p_t1, ne, 384, 416);
    // layer 2 fused with rbfh and xh[src] gather
    gemm3_fused<<<dim3(3, (ne + BM - 1) / BM), blk>>>(p_t1, iw2, ib2, p_m, p_xh, ei, ne);
    // message build + segment sum
    scatter_kernel<<<((size_t)ne * 32 + 255) / 256, 256>>>(p_m, vec, ei, ev, dx, dvec, ne);
}

// round 5
// speedup vs baseline: 1.4308x; 1.2795x over previous
#include <cuda_runtime.h>
#include <cuda_bf16.h>
#include <cstdint>

// ===========================================================================
// LEFTNet layer. Edge GEMMs via mma.sync bf16 (3-term split), rest FFMA2.
// ===========================================================================

#define NN_MAX 50000
#define NE_MAX 500000

__device__ float g_h1[(size_t)NN_MAX * 128];
__device__ float g_xh[(size_t)NN_MAX * 384];
__device__ float g_m [(size_t)NE_MAX * 384];
__device__ __align__(16) __nv_bfloat16 g_whi [(size_t)NE_MAX * 448];
__device__ __align__(16) __nv_bfloat16 g_wlo [(size_t)NE_MAX * 448];
__device__ __align__(16) __nv_bfloat16 g_t1hi[(size_t)NE_MAX * 384];
__device__ __align__(16) __nv_bfloat16 g_t1lo[(size_t)NE_MAX * 384];
__device__ __align__(16) __nv_bfloat16 g_b1hi[384 * 448];
__device__ __align__(16) __nv_bfloat16 g_b1lo[384 * 448];
__device__ __align__(16) __nv_bfloat16 g_b2hi[384 * 384];
__device__ __align__(16) __nv_bfloat16 g_b2lo[384 * 384];

// ---------------------------------------------------------------------------
// helpers
// ---------------------------------------------------------------------------
__device__ __forceinline__ uint32_t smem_u32(const void* p) {
    uint32_t a;
    asm("{ .reg .u64 t; cvta.to.shared.u64 t, %1; cvt.u32.u64 %0, t; }"
        : "=r"(a) : "l"(p));
    return a;
}
__device__ __forceinline__ void cp16(uint32_t s, const void* g, uint32_t nbytes) {
    asm volatile("cp.async.cg.shared.global [%0], [%1], 16, %2;"
                 :: "r"(s), "l"(g), "r"(nbytes) : "memory");
}
__device__ __forceinline__ void cp_commit() { asm volatile("cp.async.commit_group;" ::: "memory"); }
__device__ __forceinline__ void cp_wait1()  { asm volatile("cp.async.wait_group 1;" ::: "memory"); }
__device__ __forceinline__ void cp_wait0()  { asm volatile("cp.async.wait_group 0;" ::: "memory"); }

__device__ __forceinline__ uint32_t swz(uint32_t off) { return off ^ ((off >> 3) & 0x70); }

__device__ __forceinline__ void ldm_x4(uint32_t& r0, uint32_t& r1, uint32_t& r2, uint32_t& r3,
                                       uint32_t addr) {
    asm volatile("ldmatrix.sync.aligned.m8n8.x4.shared.b16 {%0, %1, %2, %3}, [%4];"
                 : "=r"(r0), "=r"(r1), "=r"(r2), "=r"(r3) : "r"(addr));
}
__device__ __forceinline__ void mma_bf16(float* c, const uint32_t* a, const uint32_t* b) {
    asm volatile("mma.sync.aligned.m16n8k16.row.col.f32.bf16.bf16.f32 "
                 "{%0, %1, %2, %3}, {%4, %5, %6, %7}, {%8, %9}, {%0, %1, %2, %3};"
                 : "+f"(c[0]), "+f"(c[1]), "+f"(c[2]), "+f"(c[3])
                 : "r"(a[0]), "r"(a[1]), "r"(a[2]), "r"(a[3]), "r"(b[0]), "r"(b[1]));
}

__device__ __forceinline__ float silu_f(float v) {
    return v * (1.0f / (1.0f + __expf(-v)));
}

// ---------------------------------------------------------------------------
// mma.sync GEMM: C[128-tile, 128-tile] = A[M,KP] @ B^T (B stored [384,KP])
// 3-pass bf16 split: Ahi*Bhi + Alo*Bhi + Ahi*Blo, fp32 accum in regs.
// EPI 0: O = silu(C + bias) -> bf16 hi/lo planes [M,384]
// EPI 1: Cm = (C + bias) * Cm * xh[srcidx]   (in place on Cm)
// grid = (ceil(M/128), 3); 256 threads; smem = 64KB dynamic (2x(16K A+16K B)).
// ---------------------------------------------------------------------------
template<int EPI>
__global__ __launch_bounds__(256)
void tc_gemm(const __nv_bfloat16* __restrict__ Ahi, const __nv_bfloat16* __restrict__ Alo,
             const __nv_bfloat16* __restrict__ Bhi, const __nv_bfloat16* __restrict__ Blo,
             int M, int KP,
             const float* __restrict__ bias,
             __nv_bfloat16* __restrict__ Ohi, __nv_bfloat16* __restrict__ Olo,
             float* __restrict__ Cm, const float* __restrict__ xh,
             const int* __restrict__ srcidx)
{
    extern __shared__ char dsm[];
    const uint32_t dbase = smem_u32(dsm);
    // buffer b: A at dbase + b*32768, B at dbase + b*32768 + 16384
    const int tid  = threadIdx.x;
    const int wid  = tid >> 5;
    const int lane = tid & 31;

    const int row0 = blockIdx.x * 128;
    const int n0c  = blockIdx.y * 128;

    const int wm = (wid >> 2) * 64;   // warp m origin in tile
    const int wn = (wid & 3) * 32;    // warp n origin in tile

    const int g   = lane >> 2;        // group id
    const int tig = lane & 3;

    // ldmatrix lane row/chunk offsets
    const int a_r  = (lane & 7) + ((lane & 8) ? 8 : 0);
    const int a_c  = (lane >> 4);                 // +0/+1 chunk16
    const int b_r  = (lane & 7) + ((lane & 16) ? 8 : 0);
    const int b_c  = ((lane >> 3) & 1);

    float acc[4][4][4];
#pragma unroll
    for (int i = 0; i < 4; i++)
#pragma unroll
        for (int j = 0; j < 4; j++)
#pragma unroll
            for (int k = 0; k < 4; k++) acc[i][j][k] = 0.0f;

    const int nch   = KP >> 6;
    const int total = 3 * nch;

    // chunk loader: 64 K-cols (128B) x (128 A rows + 128 B rows)
    auto load_chunk = [&](int c) {
        const int b    = c & 1;
        const int pass = c / nch;
        const int k0   = (c - pass * nch) << 6;
        const __nv_bfloat16* Ap = (pass == 1) ? Alo : Ahi;
        const __nv_bfloat16* Bp = (pass == 2) ? Blo : Bhi;
        const uint32_t Ab = dbase + b * 32768;
        const uint32_t Bb = Ab + 16384;
#pragma unroll
        for (int i = 0; i < 4; i++) {
            int id  = tid + i * 256;
            int r   = id >> 3, c16 = id & 7;
            int gr  = row0 + r;
            int grc = (gr < M) ? gr : (M - 1);
            cp16(Ab + swz(r * 128 + c16 * 16),
                 Ap + (size_t)grc * KP + k0 + c16 * 8, (gr < M) ? 16u : 0u);
        }
#pragma unroll
        for (int i = 0; i < 4; i++) {
            int id = tid + i * 256;
            int r  = id >> 3, c16 = id & 7;
            cp16(Bb + swz(r * 128 + c16 * 16),
                 Bp + (size_t)(n0c + r) * KP + k0 + c16 * 8, 16u);
        }
        cp_commit();
    };

    load_chunk(0);

    for (int c = 0; c < total; c++) {
        if (c + 1 < total) { load_chunk(c + 1); cp_wait1(); }
        else               { cp_wait0(); }
        __syncthreads();

        const uint32_t Ab = dbase + (c & 1) * 32768;
        const uint32_t Bb = Ab + 16384;

#pragma unroll
        for (int ks = 0; ks < 4; ks++) {
            const int cbase = ks * 2;
            uint32_t af[4][4], bf[4][2];
#pragma unroll
            for (int mt = 0; mt < 4; mt++) {
                int r = wm + mt * 16 + a_r;
                ldm_x4(af[mt][0], af[mt][1], af[mt][2], af[mt][3],
                       Ab + swz(r * 128 + (cbase + a_c) * 16));
            }
#pragma unroll
            for (int np = 0; np < 2; np++) {
                int r = wn + np * 16 + b_r;
                uint32_t r0, r1, r2, r3;
                ldm_x4(r0, r1, r2, r3, Bb + swz(r * 128 + (cbase + b_c) * 16));
                bf[np * 2 + 0][0] = r0; bf[np * 2 + 0][1] = r1;
                bf[np * 2 + 1][0] = r2; bf[np * 2 + 1][1] = r3;
            }
#pragma unroll
            for (int mt = 0; mt < 4; mt++)
#pragma unroll
                for (int nt = 0; nt < 4; nt++)
                    mma_bf16(acc[mt][nt], af[mt], bf[nt]);
        }
        __syncthreads();
    }

    // ---- epilogue: thread (g,tig) holds (row wm+mt*16+g[+8], cols wn+nt*8+tig*2,+1)
#pragma unroll
    for (int mt = 0; mt < 4; mt++) {
#pragma unroll
        for (int half = 0; half < 2; half++) {
            const int e = row0 + wm + mt * 16 + g + half * 8;
            if (e >= M) continue;
#pragma unroll
            for (int nt = 0; nt < 4; nt++) {
                const int col = n0c + wn + nt * 8 + tig * 2;
                float v0 = acc[mt][nt][half * 2 + 0] + bias[col];
                float v1 = acc[mt][nt][half * 2 + 1] + bias[col + 1];
                if (EPI == 0) {
                    float s0 = silu_f(v0), s1 = silu_f(v1);
                    __nv_bfloat16 h0 = __float2bfloat16(s0);
                    __nv_bfloat16 h1 = __float2bfloat16(s1);
                    __nv_bfloat16 l0 = __float2bfloat16(s0 - __bfloat162float(h0));
                    __nv_bfloat16 l1 = __float2bfloat16(s1 - __bfloat162float(h1));
                    uint32_t hp = (uint32_t)__bfloat16_as_ushort(h0) |
                                  ((uint32_t)__bfloat16_as_ushort(h1) << 16);
                    uint32_t lp = (uint32_t)__bfloat16_as_ushort(l0) |
                                  ((uint32_t)__bfloat16_as_ushort(l1) << 16);
                    *(uint32_t*)&Ohi[(size_t)e * 384 + col] = hp;
                    *(uint32_t*)&Olo[(size_t)e * 384 + col] = lp;
                } else {
                    const int s = srcidx[e];
                    float2 rv = *(const float2*)&Cm[(size_t)e * 384 + col];
                    float2 xv = *(const float2*)&xh[(size_t)s * 384 + col];
                    float2 o;
                    o.x = v0 * rv.x * xv.x;
                    o.y = v1 * rv.y * xv.y;
                    *(float2*)&Cm[(size_t)e * 384 + col] = o;
                }
            }
        }
    }
}

// ---------------------------------------------------------------------------
// Split fp32 [M,K] -> bf16 hi/lo planes [M,KP] (zero-padded cols K..KP)
// ---------------------------------------------------------------------------
__global__ void split_rows(const float* __restrict__ src,
                           __nv_bfloat16* __restrict__ hi,
                           __nv_bfloat16* __restrict__ lo,
                           int M, int K, int KP)
{
    const int groups = KP >> 2;
    size_t t = (size_t)blockIdx.x * blockDim.x + threadIdx.x;
    if (t >= (size_t)M * groups) return;
    int r = (int)(t / groups);
    int gidx = (int)(t - (size_t)r * groups);
    int c = gidx * 4;
    float4 v = make_float4(0.f, 0.f, 0.f, 0.f);
    if (c < K) v = *(const float4*)&src[(size_t)r * K + c];
    float a[4] = {v.x, v.y, v.z, v.w};
    unsigned long long hpk = 0ull, lpk = 0ull;
#pragma unroll
    for (int i = 0; i < 4; i++) {
        __nv_bfloat16 h = __float2bfloat16(a[i]);
        __nv_bfloat16 l = __float2bfloat16(a[i] - __bfloat162float(h));
        hpk |= (unsigned long long)__bfloat16_as_ushort(h) << (16 * i);
        lpk |= (unsigned long long)__bfloat16_as_ushort(l) << (16 * i);
    }
    *(unsigned long long*)&hi[(size_t)r * KP + c] = hpk;
    *(unsigned long long*)&lo[(size_t)r * KP + c] = lpk;
}

// Transpose+split weights: src [K,N] fp32 -> hi/lo [N,KP] bf16
__global__ void splitT(const float* __restrict__ src,
                       __nv_bfloat16* __restrict__ hi,
                       __nv_bfloat16* __restrict__ lo,
                       int K, int N, int KP)
{
    int t = blockIdx.x * blockDim.x + threadIdx.x;
    if (t >= N * KP) return;
    int n = t / KP, k = t - n * KP;
    float v = (k < K) ? src[(size_t)k * N + n] : 0.0f;
    __nv_bfloat16 h = __float2bfloat16(v);
    __nv_bfloat16 l = __float2bfloat16(v - __bfloat162float(h));
    hi[t] = h;
    lo[t] = l;
}

// ---------------------------------------------------------------------------
// FFMA2 SGEMM for the small node/rbf GEMMs
// ---------------------------------------------------------------------------
#define BM 128
#define BN 128
#define BK 16

__device__ __forceinline__ unsigned long long pack2(float lo, float hi) {
    unsigned long long r;
    asm("mov.b64 %0, {%1, %2};" : "=l"(r) : "f"(lo), "f"(hi));
    return r;
}
__device__ __forceinline__ void unpack2(unsigned long long v, float& lo, float& hi) {
    asm("mov.b64 {%0, %1}, %2;" : "=f"(lo), "=f"(hi) : "l"(v));
}
__device__ __forceinline__ void ffma2(unsigned long long& d,
                                      unsigned long long a, unsigned long long b) {
    asm("fma.rn.f32x2 %0, %1, %2, %0;" : "+l"(d) : "l"(a), "l"(b));
}

template<bool SILU>
__global__ __launch_bounds__(256, 2)
void sgemm_bias_act(const float* __restrict__ A, const float* __restrict__ B,
                    const float* __restrict__ bias, float* __restrict__ C,
                    int M, int N, int K)
{
    __shared__ float As[BK][BM + 4];
    __shared__ float Bs[BK][BN];

    const int tid  = threadIdx.x;
    const int tx   = tid & 15;
    const int ty   = tid >> 4;
    const int row0 = blockIdx.y * BM;
    const int col0 = blockIdx.x * BN;

    unsigned long long acc2[8][4];
#pragma unroll
    for (int i = 0; i < 8; i++)
#pragma unroll
        for (int j = 0; j < 4; j++) acc2[i][j] = 0ull;

    const int a_row = tid >> 2;
    const int a_seg = tid & 3;
    const int b_kk  = tid >> 5;
    const int b_c4  = (tid & 31) << 2;

    for (int k0 = 0; k0 < K; k0 += BK) {
#pragma unroll
        for (int it = 0; it < 2; it++) {
            int r  = a_row + it * 64;
            int gr = row0 + r;
            float4 v = make_float4(0.f, 0.f, 0.f, 0.f);
            if (gr < M)
                v = *(const float4*)&A[(size_t)gr * K + k0 + a_seg * 4];
            As[a_seg * 4 + 0][r] = v.x;
            As[a_seg * 4 + 1][r] = v.y;
            As[a_seg * 4 + 2][r] = v.z;
            As[a_seg * 4 + 3][r] = v.w;
        }
#pragma unroll
        for (int it = 0; it < 2; it++) {
            int kk = b_kk + it * 8;
            *(float4*)&Bs[kk][b_c4] =
                *(const float4*)&B[(size_t)(k0 + kk) * N + col0 + b_c4];
        }
        __syncthreads();

#pragma unroll
        for (int kk = 0; kk < BK; kk++) {
            float4 a0 = *(const float4*)&As[kk][ty * 4];
            float4 a1 = *(const float4*)&As[kk][64 + ty * 4];
            float4 b0 = *(const float4*)&Bs[kk][tx * 4];
            float4 b1 = *(const float4*)&Bs[kk][64 + tx * 4];
            unsigned long long bp[4] = {
                pack2(b0.x, b0.y), pack2(b0.z, b0.w),
                pack2(b1.x, b1.y), pack2(b1.z, b1.w)
            };
            float av[8] = {a0.x, a0.y, a0.z, a0.w, a1.x, a1.y, a1.z, a1.w};
#pragma unroll
            for (int i = 0; i < 8; i++) {
                unsigned long long ap = pack2(av[i], av[i]);
#pragma unroll
                for (int jp = 0; jp < 4; jp++)
                    ffma2(acc2[i][jp], ap, bp[jp]);
            }
        }
        __syncthreads();
    }

#pragma unroll
    for (int i = 0; i < 8; i++) {
        int r  = (i < 4) ? (ty * 4 + i) : (64 + ty * 4 + (i - 4));
        int gr = row0 + r;
        if (gr >= M) continue;
#pragma unroll
        for (int jg = 0; jg < 2; jg++) {
            int c  = (jg == 0) ? (tx * 4) : (64 + tx * 4);
            int gc = col0 + c;
            float4 bi = *(const float4*)&bias[gc];
            float4 o;
            unpack2(acc2[i][jg * 2 + 0], o.x, o.y);
            unpack2(acc2[i][jg * 2 + 1], o.z, o.w);
            o.x += bi.x; o.y += bi.y; o.z += bi.z; o.w += bi.w;
            if (SILU) {
                o.x = silu_f(o.x); o.y = silu_f(o.y);
                o.z = silu_f(o.z); o.w = silu_f(o.w);
            }
            *(float4*)&C[(size_t)gr * N + gc] = o;
        }
    }
}

// ---------------------------------------------------------------------------
// Scatter: one warp per edge, vector RED into dx / dvec.
// ---------------------------------------------------------------------------
__device__ __forceinline__ void red_add_v4(float* p, float4 v) {
    asm volatile("red.global.add.v4.f32 [%0], {%1, %2, %3, %4};"
                 :: "l"(p), "f"(v.x), "f"(v.y), "f"(v.z), "f"(v.w) : "memory");
}

__global__ void scatter_kernel(const float* __restrict__ m,
                               const float* __restrict__ vec,
                               const int*   __restrict__ ei,
                               const float* __restrict__ ev,
                               float* __restrict__ dx,
                               float* __restrict__ dvec,
                               int E)
{
    int gtid = blockIdx.x * blockDim.x + threadIdx.x;
    int e    = gtid >> 5;
    int lane = gtid & 31;
    if (e >= E) return;

    int s = ei[e];
    int d = ei[E + e];

    const float4* m4 = (const float4*)(m + (size_t)e * 384);
    float4 xm = m4[lane];
    float4 h2 = m4[32 + lane];
    float4 h3 = m4[64 + lane];

    const float is3 = 0.57735026918962576f;
    const float ish = 0.08838834764831845f;
    h2.x *= is3; h2.y *= is3; h2.z *= is3; h2.w *= is3;

    float evd[3];
    evd[0] = ev[(size_t)e * 3 + 0];
    evd[1] = ev[(size_t)e * 3 + 1];
    evd[2] = ev[(size_t)e * 3 + 2];

    red_add_v4(dx + (size_t)d * 128 + lane * 4, xm);

    const float4* v4 = (const float4*)(vec + (size_t)s * 384);
#pragma unroll
    for (int t = 0; t < 3; t++) {
        float4 v = v4[t * 32 + lane];
        float4 o;
        o.x = (v.x * h2.x + h3.x * evd[t]) * ish;
        o.y = (v.y * h2.y + h3.y * evd[t]) * ish;
        o.z = (v.z * h2.z + h3.z * evd[t]) * ish;
        o.w = (v.w * h2.w + h3.w * evd[t]) * ish;
        red_add_v4(dvec + ((size_t)d * 3 + t) * 128 + lane * 4, o);
    }
}

// ---------------------------------------------------------------------------
// Launch
// ---------------------------------------------------------------------------
extern "C" void kernel_launch(void* const* d_in, const int* in_sizes, int n_in,
                              void* d_out, int out_size)
{
    const float* x    = (const float*)d_in[0];
    const float* vec  = (const float*)d_in[1];
    const int*   ei   = (const int*)  d_in[2];
    const float* rbf  = (const float*)d_in[3];
    const float* wgt  = (const float*)d_in[4];
    const float* ev   = (const float*)d_in[5];
    const float* xw1  = (const float*)d_in[6];
    const float* xb1  = (const float*)d_in[7];
    const float* xw2  = (const float*)d_in[8];
    const float* xb2  = (const float*)d_in[9];
    const float* rw   = (const float*)d_in[10];
    const float* rb   = (const float*)d_in[11];
    const float* iw1  = (const float*)d_in[12];
    const float* ib1  = (const float*)d_in[13];
    const float* iw2  = (const float*)d_in[14];
    const float* ib2  = (const float*)d_in[15];

    const int nn = in_sizes[0] / 128;
    const int ne = in_sizes[2] / 2;

    float* out  = (float*)d_out;
    float* dx   = out;
    float* dvec = out + (size_t)nn * 128;

    float *p_h1, *p_xh, *p_m;
    __nv_bfloat16 *p_whi, *p_wlo, *p_t1hi, *p_t1lo, *p_b1hi, *p_b1lo, *p_b2hi, *p_b2lo;
    cudaGetSymbolAddress((void**)&p_h1,  g_h1);
    cudaGetSymbolAddress((void**)&p_xh,  g_xh);
    cudaGetSymbolAddress((void**)&p_m,   g_m);
    cudaGetSymbolAddress((void**)&p_whi, g_whi);
    cudaGetSymbolAddress((void**)&p_wlo, g_wlo);
    cudaGetSymbolAddress((void**)&p_t1hi, g_t1hi);
    cudaGetSymbolAddress((void**)&p_t1lo, g_t1lo);
    cudaGetSymbolAddress((void**)&p_b1hi, g_b1hi);
    cudaGetSymbolAddress((void**)&p_b1lo, g_b1lo);
    cudaGetSymbolAddress((void**)&p_b2hi, g_b2hi);
    cudaGetSymbolAddress((void**)&p_b2lo, g_b2lo);

    const int TC_SMEM = 65536;
    cudaFuncSetAttribute(tc_gemm<0>, cudaFuncAttributeMaxDynamicSharedMemorySize, TC_SMEM);
    cudaFuncSetAttribute(tc_gemm<1>, cudaFuncAttributeMaxDynamicSharedMemorySize, TC_SMEM);

    cudaMemsetAsync(d_out, 0, (size_t)out_size * sizeof(float));

    dim3 blk(256);

    // convert inputs for the tensor-core path
    {
        size_t total = (size_t)ne * (448 / 4);
        split_rows<<<(unsigned)((total + 255) / 256), blk>>>(wgt, p_whi, p_wlo, ne, 416, 448);
    }
    splitT<<<(384 * 448 + 255) / 256, blk>>>(iw1, p_b1hi, p_b1lo, 416, 384, 448);
    splitT<<<(384 * 384 + 255) / 256, blk>>>(iw2, p_b2hi, p_b2lo, 384, 384, 384);

    // node projection (FFMA2)
    sgemm_bias_act<true ><<<dim3(1, (nn + BM - 1) / BM), blk>>>(x,    xw1, xb1, p_h1, nn, 128, 128);
    sgemm_bias_act<false><<<dim3(3, (nn + BM - 1) / BM), blk>>>(p_h1, xw2, xb2, p_xh, nn, 384, 128);
    // edge radial filter: g_m = rbf@rw + rb (FFMA2)
    sgemm_bias_act<false><<<dim3(3, (ne + BM - 1) / BM), blk>>>(rbf,  rw,  rb,  p_m,  ne, 384, 32);

    const int mtiles = (ne + 127) / 128;
    // t1 = silu(weight@iw1 + ib1)  -> bf16 hi/lo planes
    tc_gemm<0><<<dim3(mtiles, 3), blk, TC_SMEM>>>(p_whi, p_wlo, p_b1hi, p_b1lo, ne, 448, ib1,
                                                  p_t1hi, p_t1lo, nullptr, nullptr, nullptr);
    // g_m = (t1@iw2 + ib2) * g_m * xh[src]
    tc_gemm<1><<<dim3(mtiles, 3), blk, TC_SMEM>>>(p_t1hi, p_t1lo, p_b2hi, p_b2lo, ne, 384, ib2,
                                                  nullptr, nullptr, p_m, p_xh, ei);

    // message build + segment sum
    scatter_kernel<<<(unsigned)(((size_t)ne * 32 + 255) / 256), 256>>>(p_m, vec, ei, ev, dx, dvec, ne);
}

// round 6
// speedup vs baseline: 1.5593x; 1.0898x over previous
#include <cuda_runtime.h>
#include <cuda_bf16.h>
#include <cstdint>

// ===========================================================================
// LEFTNet layer. Edge GEMMs via mma.sync bf16 (3-term split), full-N CTAs,
// scatter fused into gemm5 epilogue. Node/rbf GEMMs on FFMA2.
// ===========================================================================

#define NN_MAX 50000
#define NE_MAX 500000

__device__ float g_h1[(size_t)NN_MAX * 128];
__device__ float g_xh[(size_t)NN_MAX * 384];
__device__ float g_m [(size_t)NE_MAX * 384];      // rbfh
__device__ __align__(16) __nv_bfloat16 g_whi [(size_t)NE_MAX * 448];
__device__ __align__(16) __nv_bfloat16 g_wlo [(size_t)NE_MAX * 448];
__device__ __align__(16) __nv_bfloat16 g_t1hi[(size_t)NE_MAX * 384];
__device__ __align__(16) __nv_bfloat16 g_t1lo[(size_t)NE_MAX * 384];
__device__ __align__(16) __nv_bfloat16 g_b1hi[384 * 448];
__device__ __align__(16) __nv_bfloat16 g_b1lo[384 * 448];
__device__ __align__(16) __nv_bfloat16 g_b2hi[384 * 384];
__device__ __align__(16) __nv_bfloat16 g_b2lo[384 * 384];

// ---------------------------------------------------------------------------
// helpers
// ---------------------------------------------------------------------------
__device__ __forceinline__ uint32_t smem_u32(const void* p) {
    uint32_t a;
    asm("{ .reg .u64 t; cvta.to.shared.u64 t, %1; cvt.u32.u64 %0, t; }"
        : "=r"(a) : "l"(p));
    return a;
}
__device__ __forceinline__ void cp16(uint32_t s, const void* g, uint32_t nbytes) {
    asm volatile("cp.async.cg.shared.global [%0], [%1], 16, %2;"
                 :: "r"(s), "l"(g), "r"(nbytes) : "memory");
}
__device__ __forceinline__ void cp_commit() { asm volatile("cp.async.commit_group;" ::: "memory"); }
__device__ __forceinline__ void cp_wait1()  { asm volatile("cp.async.wait_group 1;" ::: "memory"); }
__device__ __forceinline__ void cp_wait0()  { asm volatile("cp.async.wait_group 0;" ::: "memory"); }

__device__ __forceinline__ uint32_t swz(uint32_t off) { return off ^ ((off >> 3) & 0x70); }

__device__ __forceinline__ void ldm_x4(uint32_t& r0, uint32_t& r1, uint32_t& r2, uint32_t& r3,
                                       uint32_t addr) {
    asm volatile("ldmatrix.sync.aligned.m8n8.x4.shared.b16 {%0, %1, %2, %3}, [%4];"
                 : "=r"(r0), "=r"(r1), "=r"(r2), "=r"(r3) : "r"(addr));
}
__device__ __forceinline__ void mma_bf16(float* c, const uint32_t* a, const uint32_t* b) {
    asm volatile("mma.sync.aligned.m16n8k16.row.col.f32.bf16.bf16.f32 "
                 "{%0, %1, %2, %3}, {%4, %5, %6, %7}, {%8, %9}, {%0, %1, %2, %3};"
                 : "+f"(c[0]), "+f"(c[1]), "+f"(c[2]), "+f"(c[3])
                 : "r"(a[0]), "r"(a[1]), "r"(a[2]), "r"(a[3]), "r"(b[0]), "r"(b[1]));
}
__device__ __forceinline__ void red_add_v4(float* p, float4 v) {
    asm volatile("red.global.add.v4.f32 [%0], {%1, %2, %3, %4};"
                 :: "l"(p), "f"(v.x), "f"(v.y), "f"(v.z), "f"(v.w) : "memory");
}
__device__ __forceinline__ float silu_f(float v) {
    return v * (1.0f / (1.0f + __expf(-v)));
}

// ---------------------------------------------------------------------------
// mma.sync GEMM: C[64-tile, 384] = A[M,KP] @ B^T (B stored [384,KP])
// 3 sequential passes: Ahi*Bhi, Alo*Bhi, Ahi*Blo. fp32 accum in regs.
// 256 threads, 8 warps = 2m x 4n (warp tile 32 x 96). acc = 96 f32/thread.
// smem: 2 stages x (A 8KB + B 48KB) = 112 KB (+ epilogue staging aliased).
// EPI 0: O = silu(C + bias) -> bf16 hi/lo planes [M,384]
// EPI 1: fused message + scatter:
//        m = (C+bias) * rbfh[e] * xh[src[e]]; split; RED into dx/dvec.
// ---------------------------------------------------------------------------
#define STAGE_BYTES 57344

template<int EPI>
__global__ __launch_bounds__(256)
void tc_gemm(const __nv_bfloat16* __restrict__ Ahi, const __nv_bfloat16* __restrict__ Alo,
             const __nv_bfloat16* __restrict__ Bhi, const __nv_bfloat16* __restrict__ Blo,
             int M, int KP,
             const float* __restrict__ bias,
             __nv_bfloat16* __restrict__ Ohi, __nv_bfloat16* __restrict__ Olo,
             const float* __restrict__ rbfh, const float* __restrict__ xh,
             const int* __restrict__ ei, int E,
             const float* __restrict__ vec, const float* __restrict__ ev,
             float* __restrict__ dx, float* __restrict__ dvec)
{
    extern __shared__ char dsm[];
    const uint32_t dbase = smem_u32(dsm);
    float* m_st = (float*)dsm;                 // epilogue staging: [64][388]

    const int tid  = threadIdx.x;
    const int wid  = tid >> 5;
    const int lane = tid & 31;

    const int row0 = blockIdx.x * 64;

    const int wm = (wid >> 2) * 32;            // 0 / 32
    const int wn = (wid & 3) * 96;             // 0 / 96 / 192 / 288

    const int g   = lane >> 2;
    const int tig = lane & 3;

    const int a_r  = (lane & 7) + ((lane & 8) ? 8 : 0);
    const int a_c  = (lane >> 4);
    const int b_r  = (lane & 7) + ((lane & 16) ? 8 : 0);
    const int b_c  = ((lane >> 3) & 1);

    float acc[2][12][4];
#pragma unroll
    for (int i = 0; i < 2; i++)
#pragma unroll
        for (int j = 0; j < 12; j++)
#pragma unroll
            for (int k = 0; k < 4; k++) acc[i][j][k] = 0.0f;

    const int nch   = KP >> 6;
    const int total = 3 * nch;

    auto load_chunk = [&](int c) {
        const int b    = c & 1;
        const int pass = c / nch;
        const int k0   = (c - pass * nch) << 6;
        const __nv_bfloat16* Ap = (pass == 1) ? Alo : Ahi;
        const __nv_bfloat16* Bp = (pass == 2) ? Blo : Bhi;
        const uint32_t Ab = dbase + b * STAGE_BYTES;
        const uint32_t Bb = Ab + 8192;
        // A: 64 rows x 8 x 16B = 512 units
#pragma unroll
        for (int i = 0; i < 2; i++) {
            int id  = tid + i * 256;
            int r   = id >> 3, c16 = id & 7;
            int gr  = row0 + r;
            int grc = (gr < M) ? gr : (M - 1);
            cp16(Ab + swz(r * 128 + c16 * 16),
                 Ap + (size_t)grc * KP + k0 + c16 * 8, (gr < M) ? 16u : 0u);
        }
        // B: 384 rows x 8 x 16B = 3072 units
#pragma unroll
        for (int i = 0; i < 12; i++) {
            int id = tid + i * 256;
            int r  = id >> 3, c16 = id & 7;
            cp16(Bb + swz(r * 128 + c16 * 16),
                 Bp + (size_t)r * KP + k0 + c16 * 8, 16u);
        }
        cp_commit();
    };

    load_chunk(0);

    for (int c = 0; c < total; c++) {
        if (c + 1 < total) { load_chunk(c + 1); cp_wait1(); }
        else               { cp_wait0(); }
        __syncthreads();

        const uint32_t Ab = dbase + (c & 1) * STAGE_BYTES;
        const uint32_t Bb = Ab + 8192;

#pragma unroll
        for (int ks = 0; ks < 4; ks++) {
            const int cbase = ks * 2;
            uint32_t af[2][4], bf[12][2];
#pragma unroll
            for (int mt = 0; mt < 2; mt++) {
                int r = wm + mt * 16 + a_r;
                ldm_x4(af[mt][0], af[mt][1], af[mt][2], af[mt][3],
                       Ab + swz(r * 128 + (cbase + a_c) * 16));
            }
#pragma unroll
            for (int np = 0; np < 6; np++) {
                int r = wn + np * 16 + b_r;
                uint32_t r0, r1, r2, r3;
                ldm_x4(r0, r1, r2, r3, Bb + swz(r * 128 + (cbase + b_c) * 16));
                bf[np * 2 + 0][0] = r0; bf[np * 2 + 0][1] = r1;
                bf[np * 2 + 1][0] = r2; bf[np * 2 + 1][1] = r3;
            }
#pragma unroll
            for (int mt = 0; mt < 2; mt++)
#pragma unroll
                for (int nt = 0; nt < 12; nt++)
                    mma_bf16(acc[mt][nt], af[mt], bf[nt]);
        }
        __syncthreads();
    }

    if (EPI == 0) {
        // write silu(C+bias) as bf16 hi/lo planes
#pragma unroll
        for (int mt = 0; mt < 2; mt++) {
#pragma unroll
            for (int half = 0; half < 2; half++) {
                const int e = row0 + wm + mt * 16 + g + half * 8;
                if (e >= M) continue;
#pragma unroll
                for (int nt = 0; nt < 12; nt++) {
                    const int col = wn + nt * 8 + tig * 2;
                    float v0 = acc[mt][nt][half * 2 + 0] + bias[col];
                    float v1 = acc[mt][nt][half * 2 + 1] + bias[col + 1];
                    float s0 = silu_f(v0), s1 = silu_f(v1);
                    __nv_bfloat16 h0 = __float2bfloat16(s0);
                    __nv_bfloat16 h1 = __float2bfloat16(s1);
                    __nv_bfloat16 l0 = __float2bfloat16(s0 - __bfloat162float(h0));
                    __nv_bfloat16 l1 = __float2bfloat16(s1 - __bfloat162float(h1));
                    uint32_t hp = (uint32_t)__bfloat16_as_ushort(h0) |
                                  ((uint32_t)__bfloat16_as_ushort(h1) << 16);
                    uint32_t lp = (uint32_t)__bfloat16_as_ushort(l0) |
                                  ((uint32_t)__bfloat16_as_ushort(l1) << 16);
                    *(uint32_t*)&Ohi[(size_t)e * 384 + col] = hp;
                    *(uint32_t*)&Olo[(size_t)e * 384 + col] = lp;
                }
            }
        }
    } else {
        // ---- fused scatter epilogue ----
        // stage C+bias to smem [64][388]
#pragma unroll
        for (int mt = 0; mt < 2; mt++) {
#pragma unroll
            for (int half = 0; half < 2; half++) {
                const int er = wm + mt * 16 + g + half * 8;
#pragma unroll
                for (int nt = 0; nt < 12; nt++) {
                    const int col = wn + nt * 8 + tig * 2;
                    m_st[er * 388 + col]     = acc[mt][nt][half * 2 + 0] + bias[col];
                    m_st[er * 388 + col + 1] = acc[mt][nt][half * 2 + 1] + bias[col + 1];
                }
            }
        }
        __syncthreads();

        const float is3 = 0.57735026918962576f;   // 1/sqrt(3)
        const float ish = 0.08838834764831845f;   // 1/sqrt(128)

        // warp-per-edge: 8 warps x 8 edges
#pragma unroll
        for (int i = 0; i < 8; i++) {
            const int er = wid * 8 + i;
            const int e  = row0 + er;
            if (e >= M) continue;
            const int s = ei[e];
            const int d = ei[E + e];

            const float* st = m_st + er * 388;
            float4 a0 = *(const float4*)&st[lane * 4];
            float4 a1 = *(const float4*)&st[128 + lane * 4];
            float4 a2 = *(const float4*)&st[256 + lane * 4];

            const float* rr = rbfh + (size_t)e * 384;
            const float* xr = xh   + (size_t)s * 384;
            float4 r0 = *(const float4*)&rr[lane * 4];
            float4 r1 = *(const float4*)&rr[128 + lane * 4];
            float4 r2 = *(const float4*)&rr[256 + lane * 4];
            float4 x0 = *(const float4*)&xr[lane * 4];
            float4 x1 = *(const float4*)&xr[128 + lane * 4];
            float4 x2 = *(const float4*)&xr[256 + lane * 4];

            float4 xm, h2, h3;
            xm.x = a0.x * r0.x * x0.x;  xm.y = a0.y * r0.y * x0.y;
            xm.z = a0.z * r0.z * x0.z;  xm.w = a0.w * r0.w * x0.w;
            h2.x = a1.x * r1.x * x1.x * is3;  h2.y = a1.y * r1.y * x1.y * is3;
            h2.z = a1.z * r1.z * x1.z * is3;  h2.w = a1.w * r1.w * x1.w * is3;
            h3.x = a2.x * r2.x * x2.x;  h3.y = a2.y * r2.y * x2.y;
            h3.z = a2.z * r2.z * x2.z;  h3.w = a2.w * r2.w * x2.w;

            red_add_v4(dx + (size_t)d * 128 + lane * 4, xm);

            float evd0 = __ldg(&ev[(size_t)e * 3 + 0]);
            float evd1 = __ldg(&ev[(size_t)e * 3 + 1]);
            float evd2 = __ldg(&ev[(size_t)e * 3 + 2]);
            const float4* v4 = (const float4*)(vec + (size_t)s * 384);
            float evd[3] = {evd0, evd1, evd2};
#pragma unroll
            for (int t = 0; t < 3; t++) {
                float4 v = v4[t * 32 + lane];
                float4 o;
                o.x = (v.x * h2.x + h3.x * evd[t]) * ish;
                o.y = (v.y * h2.y + h3.y * evd[t]) * ish;
                o.z = (v.z * h2.z + h3.z * evd[t]) * ish;
                o.w = (v.w * h2.w + h3.w * evd[t]) * ish;
                red_add_v4(dvec + ((size_t)d * 3 + t) * 128 + lane * 4, o);
            }
        }
    }
}

// ---------------------------------------------------------------------------
// Split fp32 [M,K] -> bf16 hi/lo planes [M,KP] (zero-padded cols K..KP)
// ---------------------------------------------------------------------------
__global__ void split_rows(const float* __restrict__ src,
                           __nv_bfloat16* __restrict__ hi,
                           __nv_bfloat16* __restrict__ lo,
                           int M, int K, int KP)
{
    const int groups = KP >> 2;
    size_t t = (size_t)blockIdx.x * blockDim.x + threadIdx.x;
    if (t >= (size_t)M * groups) return;
    int r = (int)(t / groups);
    int gidx = (int)(t - (size_t)r * groups);
    int c = gidx * 4;
    float4 v = make_float4(0.f, 0.f, 0.f, 0.f);
    if (c < K) v = *(const float4*)&src[(size_t)r * K + c];
    float a[4] = {v.x, v.y, v.z, v.w};
    unsigned long long hpk = 0ull, lpk = 0ull;
#pragma unroll
    for (int i = 0; i < 4; i++) {
        __nv_bfloat16 h = __float2bfloat16(a[i]);
        __nv_bfloat16 l = __float2bfloat16(a[i] - __bfloat162float(h));
        hpk |= (unsigned long long)__bfloat16_as_ushort(h) << (16 * i);
        lpk |= (unsigned long long)__bfloat16_as_ushort(l) << (16 * i);
    }
    *(unsigned long long*)&hi[(size_t)r * KP + c] = hpk;
    *(unsigned long long*)&lo[(size_t)r * KP + c] = lpk;
}

__global__ void splitT(const float* __restrict__ src,
                       __nv_bfloat16* __restrict__ hi,
                       __nv_bfloat16* __restrict__ lo,
                       int K, int N, int KP)
{
    int t = blockIdx.x * blockDim.x + threadIdx.x;
    if (t >= N * KP) return;
    int n = t / KP, k = t - n * KP;
    float v = (k < K) ? src[(size_t)k * N + n] : 0.0f;
    __nv_bfloat16 h = __float2bfloat16(v);
    __nv_bfloat16 l = __float2bfloat16(v - __bfloat162float(h));
    hi[t] = h;
    lo[t] = l;
}

// ---------------------------------------------------------------------------
// FFMA2 SGEMM for the small node/rbf GEMMs
// ---------------------------------------------------------------------------
#define BM 128
#define BN 128
#define BK 16

__device__ __forceinline__ unsigned long long pack2(float lo, float hi) {
    unsigned long long r;
    asm("mov.b64 %0, {%1, %2};" : "=l"(r) : "f"(lo), "f"(hi));
    return r;
}
__device__ __forceinline__ void unpack2(unsigned long long v, float& lo, float& hi) {
    asm("mov.b64 {%0, %1}, %2;" : "=f"(lo), "=f"(hi) : "l"(v));
}
__device__ __forceinline__ void ffma2(unsigned long long& d,
                                      unsigned long long a, unsigned long long b) {
    asm("fma.rn.f32x2 %0, %1, %2, %0;" : "+l"(d) : "l"(a), "l"(b));
}

template<bool SILU>
__global__ __launch_bounds__(256, 2)
void sgemm_bias_act(const float* __restrict__ A, const float* __restrict__ B,
                    const float* __restrict__ bias, float* __restrict__ C,
                    int M, int N, int K)
{
    __shared__ float As[BK][BM + 4];
    __shared__ float Bs[BK][BN];

    const int tid  = threadIdx.x;
    const int tx   = tid & 15;
    const int ty   = tid >> 4;
    const int row0 = blockIdx.y * BM;
    const int col0 = blockIdx.x * BN;

    unsigned long long acc2[8][4];
#pragma unroll
    for (int i = 0; i < 8; i++)
#pragma unroll
        for (int j = 0; j < 4; j++) acc2[i][j] = 0ull;

    const int a_row = tid >> 2;
    const int a_seg = tid & 3;
    const int b_kk  = tid >> 5;
    const int b_c4  = (tid & 31) << 2;

    for (int k0 = 0; k0 < K; k0 += BK) {
#pragma unroll
        for (int it = 0; it < 2; it++) {
            int r  = a_row + it * 64;
            int gr = row0 + r;
            float4 v = make_float4(0.f, 0.f, 0.f, 0.f);
            if (gr < M)
                v = *(const float4*)&A[(size_t)gr * K + k0 + a_seg * 4];
            As[a_seg * 4 + 0][r] = v.x;
            As[a_seg * 4 + 1][r] = v.y;
            As[a_seg * 4 + 2][r] = v.z;
            As[a_seg * 4 + 3][r] = v.w;
        }
#pragma unroll
        for (int it = 0; it < 2; it++) {
            int kk = b_kk + it * 8;
            *(float4*)&Bs[kk][b_c4] =
                *(const float4*)&B[(size_t)(k0 + kk) * N + col0 + b_c4];
        }
        __syncthreads();

#pragma unroll
        for (int kk = 0; kk < BK; kk++) {
            float4 a0 = *(const float4*)&As[kk][ty * 4];
            float4 a1 = *(const float4*)&As[kk][64 + ty * 4];
            float4 b0 = *(const float4*)&Bs[kk][tx * 4];
            float4 b1 = *(const float4*)&Bs[kk][64 + tx * 4];
            unsigned long long bp[4] = {
                pack2(b0.x, b0.y), pack2(b0.z, b0.w),
                pack2(b1.x, b1.y), pack2(b1.z, b1.w)
            };
            float av[8] = {a0.x, a0.y, a0.z, a0.w, a1.x, a1.y, a1.z, a1.w};
#pragma unroll
            for (int i = 0; i < 8; i++) {
                unsigned long long ap = pack2(av[i], av[i]);
#pragma unroll
                for (int jp = 0; jp < 4; jp++)
                    ffma2(acc2[i][jp], ap, bp[jp]);
            }
        }
        __syncthreads();
    }

#pragma unroll
    for (int i = 0; i < 8; i++) {
        int r  = (i < 4) ? (ty * 4 + i) : (64 + ty * 4 + (i - 4));
        int gr = row0 + r;
        if (gr >= M) continue;
#pragma unroll
        for (int jg = 0; jg < 2; jg++) {
            int c  = (jg == 0) ? (tx * 4) : (64 + tx * 4);
            int gc = col0 + c;
            float4 bi = *(const float4*)&bias[gc];
            float4 o;
            unpack2(acc2[i][jg * 2 + 0], o.x, o.y);
            unpack2(acc2[i][jg * 2 + 1], o.z, o.w);
            o.x += bi.x; o.y += bi.y; o.z += bi.z; o.w += bi.w;
            if (SILU) {
                o.x = silu_f(o.x); o.y = silu_f(o.y);
                o.z = silu_f(o.z); o.w = silu_f(o.w);
            }
            *(float4*)&C[(size_t)gr * N + gc] = o;
        }
    }
}

// ---------------------------------------------------------------------------
// Launch
// ---------------------------------------------------------------------------
extern "C" void kernel_launch(void* const* d_in, const int* in_sizes, int n_in,
                              void* d_out, int out_size)
{
    const float* x    = (const float*)d_in[0];
    const float* vec  = (const float*)d_in[1];
    const int*   ei   = (const int*)  d_in[2];
    const float* rbf  = (const float*)d_in[3];
    const float* wgt  = (const float*)d_in[4];
    const float* ev   = (const float*)d_in[5];
    const float* xw1  = (const float*)d_in[6];
    const float* xb1  = (const float*)d_in[7];
    const float* xw2  = (const float*)d_in[8];
    const float* xb2  = (const float*)d_in[9];
    const float* rw   = (const float*)d_in[10];
    const float* rb   = (const float*)d_in[11];
    const float* iw1  = (const float*)d_in[12];
    const float* ib1  = (const float*)d_in[13];
    const float* iw2  = (const float*)d_in[14];
    const float* ib2  = (const float*)d_in[15];

    const int nn = in_sizes[0] / 128;
    const int ne = in_sizes[2] / 2;

    float* out  = (float*)d_out;
    float* dx   = out;
    float* dvec = out + (size_t)nn * 128;

    float *p_h1, *p_xh, *p_m;
    __nv_bfloat16 *p_whi, *p_wlo, *p_t1hi, *p_t1lo, *p_b1hi, *p_b1lo, *p_b2hi, *p_b2lo;
    cudaGetSymbolAddress((void**)&p_h1,  g_h1);
    cudaGetSymbolAddress((void**)&p_xh,  g_xh);
    cudaGetSymbolAddress((void**)&p_m,   g_m);
    cudaGetSymbolAddress((void**)&p_whi, g_whi);
    cudaGetSymbolAddress((void**)&p_wlo, g_wlo);
    cudaGetSymbolAddress((void**)&p_t1hi, g_t1hi);
    cudaGetSymbolAddress((void**)&p_t1lo, g_t1lo);
    cudaGetSymbolAddress((void**)&p_b1hi, g_b1hi);
    cudaGetSymbolAddress((void**)&p_b1lo, g_b1lo);
    cudaGetSymbolAddress((void**)&p_b2hi, g_b2hi);
    cudaGetSymbolAddress((void**)&p_b2lo, g_b2lo);

    const int TC_SMEM = 2 * STAGE_BYTES;   // 114688
    cudaFuncSetAttribute(tc_gemm<0>, cudaFuncAttributeMaxDynamicSharedMemorySize, TC_SMEM);
    cudaFuncSetAttribute(tc_gemm<1>, cudaFuncAttributeMaxDynamicSharedMemorySize, TC_SMEM);

    cudaMemsetAsync(d_out, 0, (size_t)out_size * sizeof(float));

    dim3 blk(256);

    // conversions for the tensor-core path
    {
        size_t total = (size_t)ne * (448 / 4);
        split_rows<<<(unsigned)((total + 255) / 256), blk>>>(wgt, p_whi, p_wlo, ne, 416, 448);
    }
    splitT<<<(384 * 448 + 255) / 256, blk>>>(iw1, p_b1hi, p_b1lo, 416, 384, 448);
    splitT<<<(384 * 384 + 255) / 256, blk>>>(iw2, p_b2hi, p_b2lo, 384, 384, 384);

    // node projection (FFMA2)
    sgemm_bias_act<true ><<<dim3(1, (nn + BM - 1) / BM), blk>>>(x,    xw1, xb1, p_h1, nn, 128, 128);
    sgemm_bias_act<false><<<dim3(3, (nn + BM - 1) / BM), blk>>>(p_h1, xw2, xb2, p_xh, nn, 384, 128);
    // edge radial filter: g_m = rbf@rw + rb (FFMA2)
    sgemm_bias_act<false><<<dim3(3, (ne + BM - 1) / BM), blk>>>(rbf,  rw,  rb,  p_m,  ne, 384, 32);

    const int mtiles = (ne + 63) / 64;
    // t1 = silu(weight@iw1 + ib1) -> bf16 hi/lo planes
    tc_gemm<0><<<mtiles, blk, TC_SMEM>>>(p_whi, p_wlo, p_b1hi, p_b1lo, ne, 448, ib1,
                                         p_t1hi, p_t1lo,
                                         nullptr, nullptr, nullptr, 0,
                                         nullptr, nullptr, nullptr, nullptr);
    // fused: w2 = t1@iw2+ib2; m = w2*rbfh*xh[src]; scatter RED into dx/dvec
    tc_gemm<1><<<mtiles, blk, TC_SMEM>>>(p_t1hi, p_t1lo, p_b2hi, p_b2lo, ne, 384, ib2,
                                         nullptr, nullptr,
                                         p_m, p_xh, ei, ne,
                                         vec, ev, dx, dvec);
}

// round 7
// speedup vs baseline: 1.6089x; 1.0318x over previous
#include <cuda_runtime.h>
#include <cuda_bf16.h>
#include <cstdint>

// ===========================================================================
// LEFTNet layer. Edge GEMMs via mma.sync bf16 (3-term split) with smem-
// resident A (loaded/converted once per CTA); scatter fused into gemm5.
// ===========================================================================

#define NN_MAX 50000
#define NE_MAX 500000

__device__ float g_h1[(size_t)NN_MAX * 128];
__device__ float g_xh[(size_t)NN_MAX * 384];
__device__ float g_m [(size_t)NE_MAX * 384];      // rbfh
__device__ __align__(16) __nv_bfloat16 g_t1hi[(size_t)NE_MAX * 384];
__device__ __align__(16) __nv_bfloat16 g_t1lo[(size_t)NE_MAX * 384];
__device__ __align__(16) __nv_bfloat16 g_b1hi[384 * 448];
__device__ __align__(16) __nv_bfloat16 g_b1lo[384 * 448];
__device__ __align__(16) __nv_bfloat16 g_b2hi[384 * 384];
__device__ __align__(16) __nv_bfloat16 g_b2lo[384 * 384];

// ---------------------------------------------------------------------------
// helpers
// ---------------------------------------------------------------------------
__device__ __forceinline__ uint32_t smem_u32(const void* p) {
    uint32_t a;
    asm("{ .reg .u64 t; cvta.to.shared.u64 t, %1; cvt.u32.u64 %0, t; }"
        : "=r"(a) : "l"(p));
    return a;
}
__device__ __forceinline__ void cp16(uint32_t s, const void* g, uint32_t nbytes) {
    asm volatile("cp.async.cg.shared.global [%0], [%1], 16, %2;"
                 :: "r"(s), "l"(g), "r"(nbytes) : "memory");
}
__device__ __forceinline__ void cp_commit() { asm volatile("cp.async.commit_group;" ::: "memory"); }
__device__ __forceinline__ void cp_wait1()  { asm volatile("cp.async.wait_group 1;" ::: "memory"); }
__device__ __forceinline__ void cp_wait0()  { asm volatile("cp.async.wait_group 0;" ::: "memory"); }

__device__ __forceinline__ uint32_t swz(uint32_t off) { return off ^ ((off >> 3) & 0x70); }

__device__ __forceinline__ void ldm_x4(uint32_t& r0, uint32_t& r1, uint32_t& r2, uint32_t& r3,
                                       uint32_t addr) {
    asm volatile("ldmatrix.sync.aligned.m8n8.x4.shared.b16 {%0, %1, %2, %3}, [%4];"
                 : "=r"(r0), "=r"(r1), "=r"(r2), "=r"(r3) : "r"(addr));
}
__device__ __forceinline__ void mma_bf16(float* c, const uint32_t* a, const uint32_t* b) {
    asm volatile("mma.sync.aligned.m16n8k16.row.col.f32.bf16.bf16.f32 "
                 "{%0, %1, %2, %3}, {%4, %5, %6, %7}, {%8, %9}, {%0, %1, %2, %3};"
                 : "+f"(c[0]), "+f"(c[1]), "+f"(c[2]), "+f"(c[3])
                 : "r"(a[0]), "r"(a[1]), "r"(a[2]), "r"(a[3]), "r"(b[0]), "r"(b[1]));
}
__device__ __forceinline__ void red_add_v4(float* p, float4 v) {
    asm volatile("red.global.add.v4.f32 [%0], {%1, %2, %3, %4};"
                 :: "l"(p), "f"(v.x), "f"(v.y), "f"(v.z), "f"(v.w) : "memory");
}
__device__ __forceinline__ float silu_f(float v) {
    return v * (1.0f / (1.0f + __expf(-v)));
}

// ---------------------------------------------------------------------------
// mma.sync GEMM, A resident in smem.
// C[64-tile, 384] = A[M,KP] @ B^T (B stored [384,KP]).
// 3 passes (Ahi*Bhi, Alo*Bhi, Ahi*Blo) over B chunks; A hi/lo planes held in
// smem for the whole kernel. fp32 accum in regs, warp tile 32x96.
// CONV=true: A comes from fp32 src (Kreal cols), converted in prologue.
// EPI 0: O = silu(C + bias) -> bf16 hi/lo planes
// EPI 1: fused message + scatter
// smem layout: [Ahi chunks nch*8K][Alo chunks nch*8K][B db 2*48K]
// ---------------------------------------------------------------------------
template<int EPI, bool CONV, int NCH>
__global__ __launch_bounds__(256)
void tc_gemm(const float* __restrict__ Afp32, int Kreal,
             const __nv_bfloat16* __restrict__ Ahi, const __nv_bfloat16* __restrict__ Alo,
             const __nv_bfloat16* __restrict__ Bhi, const __nv_bfloat16* __restrict__ Blo,
             int M,
             const float* __restrict__ bias,
             __nv_bfloat16* __restrict__ Ohi, __nv_bfloat16* __restrict__ Olo,
             const float* __restrict__ rbfh, const float* __restrict__ xh,
             const int* __restrict__ ei, int E,
             const float* __restrict__ vec, const float* __restrict__ ev,
             float* __restrict__ dx, float* __restrict__ dvec)
{
    extern __shared__ char dsm[];
    const uint32_t dbase = smem_u32(dsm);
    float* m_st = (float*)dsm;                 // EPI1 staging (aliases A region)

    constexpr int KP     = NCH * 64;
    constexpr int ABYTES = NCH * 16384;        // both planes

    const int tid  = threadIdx.x;
    const int wid  = tid >> 5;
    const int lane = tid & 31;

    const int row0 = blockIdx.x * 64;

    const int wm = (wid >> 2) * 32;
    const int wn = (wid & 3) * 96;

    const int g   = lane >> 2;
    const int tig = lane & 3;

    const int a_r  = (lane & 7) + ((lane & 8) ? 8 : 0);
    const int a_c  = (lane >> 4);
    const int b_r  = (lane & 7) + ((lane & 16) ? 8 : 0);
    const int b_c  = ((lane >> 3) & 1);

    float acc[2][12][4];
#pragma unroll
    for (int i = 0; i < 2; i++)
#pragma unroll
        for (int j = 0; j < 12; j++)
#pragma unroll
            for (int k = 0; k < 4; k++) acc[i][j][k] = 0.0f;

    const int total = 3 * NCH;

    auto load_chunk = [&](int c) {
        const int b    = c & 1;
        const int pass = c / NCH;
        const int k0   = (c - pass * NCH) << 6;
        const __nv_bfloat16* Bp = (pass == 2) ? Blo : Bhi;
        const uint32_t Bb = dbase + ABYTES + b * 49152;
#pragma unroll
        for (int i = 0; i < 12; i++) {
            int id = tid + i * 256;
            int r  = id >> 3, c16 = id & 7;
            cp16(Bb + swz(r * 128 + c16 * 16),
                 Bp + (size_t)r * KP + k0 + c16 * 8, 16u);
        }
        cp_commit();
    };

    // ---- A prologue ----
    if (CONV) {
        load_chunk(0);   // start B0 while converting
        // convert 64 x KP fp32 -> hi/lo bf16 smem (zero-pad cols >= Kreal)
        constexpr int GPR = KP / 4;            // float4 groups per row
#pragma unroll
        for (int i = 0; i < 64 * GPR / 256; i++) {
            int id   = tid + i * 256;
            int r    = id / GPR;
            int gcol = (id - r * GPR) * 4;
            int gr   = row0 + r;
            float4 v = make_float4(0.f, 0.f, 0.f, 0.f);
            if (gr < M && gcol < Kreal)
                v = *(const float4*)&Afp32[(size_t)gr * Kreal + gcol];
            float a[4] = {v.x, v.y, v.z, v.w};
            unsigned long long hpk = 0ull, lpk = 0ull;
#pragma unroll
            for (int q = 0; q < 4; q++) {
                __nv_bfloat16 h = __float2bfloat16(a[q]);
                __nv_bfloat16 l = __float2bfloat16(a[q] - __bfloat162float(h));
                hpk |= (unsigned long long)__bfloat16_as_ushort(h) << (16 * q);
                lpk |= (unsigned long long)__bfloat16_as_ushort(l) << (16 * q);
            }
            int ch = gcol >> 6, cc = gcol & 63;
            uint32_t off = ch * 8192 + swz(r * 128 + (cc >> 3) * 16 + (cc & 4) * 2);
            *(unsigned long long*)(dsm + off)               = hpk;
            *(unsigned long long*)(dsm + NCH * 8192 + off)  = lpk;
        }
    } else {
        // async-load both bf16 planes into resident chunks
        constexpr int UPC = NCH * 512;         // 16B units per plane
#pragma unroll
        for (int i = 0; i < 2 * UPC / 256; i++) {
            int id    = tid + i * 256;
            int plane = id / UPC;
            int rem   = id - plane * UPC;
            int ch    = rem >> 9;
            int r2    = (rem & 511) >> 3;
            int u     = rem & 7;
            int gr    = row0 + r2;
            int grc   = (gr < M) ? gr : (M - 1);
            const __nv_bfloat16* Ap = plane ? Alo : Ahi;
            cp16(dbase + plane * NCH * 8192 + ch * 8192 + swz(r2 * 128 + u * 16),
                 Ap + (size_t)grc * KP + ch * 64 + u * 8, (gr < M) ? 16u : 0u);
        }
        cp_commit();
        load_chunk(0);
    }

    // ---- mainloop ----
    for (int c = 0; c < total; c++) {
        if (c + 1 < total) { load_chunk(c + 1); cp_wait1(); }
        else               { cp_wait0(); }
        __syncthreads();

        const int pass = c / NCH;
        const int kch  = c - pass * NCH;
        const uint32_t Ab = dbase + (pass == 1 ? NCH * 8192 : 0) + kch * 8192;
        const uint32_t Bb = dbase + ABYTES + (c & 1) * 49152;

#pragma unroll
        for (int ks = 0; ks < 4; ks++) {
            const int cbase = ks * 2;
            uint32_t af[2][4], bf[12][2];
#pragma unroll
            for (int mt = 0; mt < 2; mt++) {
                int r = wm + mt * 16 + a_r;
                ldm_x4(af[mt][0], af[mt][1], af[mt][2], af[mt][3],
                       Ab + swz(r * 128 + (cbase + a_c) * 16));
            }
#pragma unroll
            for (int np = 0; np < 6; np++) {
                int r = wn + np * 16 + b_r;
                uint32_t r0, r1, r2, r3;
                ldm_x4(r0, r1, r2, r3, Bb + swz(r * 128 + (cbase + b_c) * 16));
                bf[np * 2 + 0][0] = r0; bf[np * 2 + 0][1] = r1;
                bf[np * 2 + 1][0] = r2; bf[np * 2 + 1][1] = r3;
            }
#pragma unroll
            for (int mt = 0; mt < 2; mt++)
#pragma unroll
                for (int nt = 0; nt < 12; nt++)
                    mma_bf16(acc[mt][nt], af[mt], bf[nt]);
        }
        __syncthreads();
    }

    if (EPI == 0) {
#pragma unroll
        for (int mt = 0; mt < 2; mt++) {
#pragma unroll
            for (int half = 0; half < 2; half++) {
                const int e = row0 + wm + mt * 16 + g + half * 8;
                if (e >= M) continue;
#pragma unroll
                for (int nt = 0; nt < 12; nt++) {
                    const int col = wn + nt * 8 + tig * 2;
                    float v0 = acc[mt][nt][half * 2 + 0] + bias[col];
                    float v1 = acc[mt][nt][half * 2 + 1] + bias[col + 1];
                    float s0 = silu_f(v0), s1 = silu_f(v1);
                    __nv_bfloat16 h0 = __float2bfloat16(s0);
                    __nv_bfloat16 h1 = __float2bfloat16(s1);
                    __nv_bfloat16 l0 = __float2bfloat16(s0 - __bfloat162float(h0));
                    __nv_bfloat16 l1 = __float2bfloat16(s1 - __bfloat162float(h1));
                    uint32_t hp = (uint32_t)__bfloat16_as_ushort(h0) |
                                  ((uint32_t)__bfloat16_as_ushort(h1) << 16);
                    uint32_t lp = (uint32_t)__bfloat16_as_ushort(l0) |
                                  ((uint32_t)__bfloat16_as_ushort(l1) << 16);
                    *(uint32_t*)&Ohi[(size_t)e * 384 + col] = hp;
                    *(uint32_t*)&Olo[(size_t)e * 384 + col] = lp;
                }
            }
        }
    } else {
        // stage C+bias to smem [64][388] (aliases A region; mainloop done)
#pragma unroll
        for (int mt = 0; mt < 2; mt++) {
#pragma unroll
            for (int half = 0; half < 2; half++) {
                const int er = wm + mt * 16 + g + half * 8;
#pragma unroll
                for (int nt = 0; nt < 12; nt++) {
                    const int col = wn + nt * 8 + tig * 2;
                    m_st[er * 388 + col]     = acc[mt][nt][half * 2 + 0] + bias[col];
                    m_st[er * 388 + col + 1] = acc[mt][nt][half * 2 + 1] + bias[col + 1];
                }
            }
        }
        __syncthreads();

        const float is3 = 0.57735026918962576f;   // 1/sqrt(3)
        const float ish = 0.08838834764831845f;   // 1/sqrt(128)

#pragma unroll
        for (int i = 0; i < 8; i++) {
            const int er = wid * 8 + i;
            const int e  = row0 + er;
            if (e >= M) continue;
            const int s = ei[e];
            const int d = ei[E + e];

            const float* st = m_st + er * 388;
            float4 a0 = *(const float4*)&st[lane * 4];
            float4 a1 = *(const float4*)&st[128 + lane * 4];
            float4 a2 = *(const float4*)&st[256 + lane * 4];

            const float* rr = rbfh + (size_t)e * 384;
            const float* xr = xh   + (size_t)s * 384;
            float4 r0 = *(const float4*)&rr[lane * 4];
            float4 r1 = *(const float4*)&rr[128 + lane * 4];
            float4 r2 = *(const float4*)&rr[256 + lane * 4];
            float4 x0 = *(const float4*)&xr[lane * 4];
            float4 x1 = *(const float4*)&xr[128 + lane * 4];
            float4 x2 = *(const float4*)&xr[256 + lane * 4];

            float4 xm, h2, h3;
            xm.x = a0.x * r0.x * x0.x;  xm.y = a0.y * r0.y * x0.y;
            xm.z = a0.z * r0.z * x0.z;  xm.w = a0.w * r0.w * x0.w;
            h2.x = a1.x * r1.x * x1.x * is3;  h2.y = a1.y * r1.y * x1.y * is3;
            h2.z = a1.z * r1.z * x1.z * is3;  h2.w = a1.w * r1.w * x1.w * is3;
            h3.x = a2.x * r2.x * x2.x;  h3.y = a2.y * r2.y * x2.y;
            h3.z = a2.z * r2.z * x2.z;  h3.w = a2.w * r2.w * x2.w;

            red_add_v4(dx + (size_t)d * 128 + lane * 4, xm);

            float evd[3];
            evd[0] = __ldg(&ev[(size_t)e * 3 + 0]);
            evd[1] = __ldg(&ev[(size_t)e * 3 + 1]);
            evd[2] = __ldg(&ev[(size_t)e * 3 + 2]);
            const float4* v4 = (const float4*)(vec + (size_t)s * 384);
#pragma unroll
            for (int t = 0; t < 3; t++) {
                float4 v = v4[t * 32 + lane];
                float4 o;
                o.x = (v.x * h2.x + h3.x * evd[t]) * ish;
                o.y = (v.y * h2.y + h3.y * evd[t]) * ish;
                o.z = (v.z * h2.z + h3.z * evd[t]) * ish;
                o.w = (v.w * h2.w + h3.w * evd[t]) * ish;
                red_add_v4(dvec + ((size_t)d * 3 + t) * 128 + lane * 4, o);
            }
        }
    }
}

// ---------------------------------------------------------------------------
// Transpose+split weights: src [K,N] fp32 -> hi/lo [N,KP] bf16
// ---------------------------------------------------------------------------
__global__ void splitT(const float* __restrict__ src,
                       __nv_bfloat16* __restrict__ hi,
                       __nv_bfloat16* __restrict__ lo,
                       int K, int N, int KP)
{
    int t = blockIdx.x * blockDim.x + threadIdx.x;
    if (t >= N * KP) return;
    int n = t / KP, k = t - n * KP;
    float v = (k < K) ? src[(size_t)k * N + n] : 0.0f;
    __nv_bfloat16 h = __float2bfloat16(v);
    __nv_bfloat16 l = __float2bfloat16(v - __bfloat162float(h));
    hi[t] = h;
    lo[t] = l;
}

// ---------------------------------------------------------------------------
// FFMA2 SGEMM for the small node/rbf GEMMs
// ---------------------------------------------------------------------------
#define BM 128
#define BN 128
#define BK 16

__device__ __forceinline__ unsigned long long pack2(float lo, float hi) {
    unsigned long long r;
    asm("mov.b64 %0, {%1, %2};" : "=l"(r) : "f"(lo), "f"(hi));
    return r;
}
__device__ __forceinline__ void unpack2(unsigned long long v, float& lo, float& hi) {
    asm("mov.b64 {%0, %1}, %2;" : "=f"(lo), "=f"(hi) : "l"(v));
}
__device__ __forceinline__ void ffma2(unsigned long long& d,
                                      unsigned long long a, unsigned long long b) {
    asm("fma.rn.f32x2 %0, %1, %2, %0;" : "+l"(d) : "l"(a), "l"(b));
}

template<bool SILU>
__global__ __launch_bounds__(256, 2)
void sgemm_bias_act(const float* __restrict__ A, const float* __restrict__ B,
                    const float* __restrict__ bias, float* __restrict__ C,
                    int M, int N, int K)
{
    __shared__ float As[BK][BM + 4];
    __shared__ float Bs[BK][BN];

    const int tid  = threadIdx.x;
    const int tx   = tid & 15;
    const int ty   = tid >> 4;
    const int row0 = blockIdx.y * BM;
    const int col0 = blockIdx.x * BN;

    unsigned long long acc2[8][4];
#pragma unroll
    for (int i = 0; i < 8; i++)
#pragma unroll
        for (int j = 0; j < 4; j++) acc2[i][j] = 0ull;

    const int a_row = tid >> 2;
    const int a_seg = tid & 3;
    const int b_kk  = tid >> 5;
    const int b_c4  = (tid & 31) << 2;

    for (int k0 = 0; k0 < K; k0 += BK) {
#pragma unroll
        for (int it = 0; it < 2; it++) {
            int r  = a_row + it * 64;
            int gr = row0 + r;
            float4 v = make_float4(0.f, 0.f, 0.f, 0.f);
            if (gr < M)
                v = *(const float4*)&A[(size_t)gr * K + k0 + a_seg * 4];
            As[a_seg * 4 + 0][r] = v.x;
            As[a_seg * 4 + 1][r] = v.y;
            As[a_seg * 4 + 2][r] = v.z;
            As[a_seg * 4 + 3][r] = v.w;
        }
#pragma unroll
        for (int it = 0; it < 2; it++) {
            int kk = b_kk + it * 8;
            *(float4*)&Bs[kk][b_c4] =
                *(const float4*)&B[(size_t)(k0 + kk) * N + col0 + b_c4];
        }
        __syncthreads();

#pragma unroll
        for (int kk = 0; kk < BK; kk++) {
            float4 a0 = *(const float4*)&As[kk][ty * 4];
            float4 a1 = *(const float4*)&As[kk][64 + ty * 4];
            float4 b0 = *(const float4*)&Bs[kk][tx * 4];
            float4 b1 = *(const float4*)&Bs[kk][64 + tx * 4];
            unsigned long long bp[4] = {
                pack2(b0.x, b0.y), pack2(b0.z, b0.w),
                pack2(b1.x, b1.y), pack2(b1.z, b1.w)
            };
            float av[8] = {a0.x, a0.y, a0.z, a0.w, a1.x, a1.y, a1.z, a1.w};
#pragma unroll
            for (int i = 0; i < 8; i++) {
                unsigned long long ap = pack2(av[i], av[i]);
#pragma unroll
                for (int jp = 0; jp < 4; jp++)
                    ffma2(acc2[i][jp], ap, bp[jp]);
            }
        }
        __syncthreads();
    }

#pragma unroll
    for (int i = 0; i < 8; i++) {
        int r  = (i < 4) ? (ty * 4 + i) : (64 + ty * 4 + (i - 4));
        int gr = row0 + r;
        if (gr >= M) continue;
#pragma unroll
        for (int jg = 0; jg < 2; jg++) {
            int c  = (jg == 0) ? (tx * 4) : (64 + tx * 4);
            int gc = col0 + c;
            float4 bi = *(const float4*)&bias[gc];
            float4 o;
            unpack2(acc2[i][jg * 2 + 0], o.x, o.y);
            unpack2(acc2[i][jg * 2 + 1], o.z, o.w);
            o.x += bi.x; o.y += bi.y; o.z += bi.z; o.w += bi.w;
            if (SILU) {
                o.x = silu_f(o.x); o.y = silu_f(o.y);
                o.z = silu_f(o.z); o.w = silu_f(o.w);
            }
            *(float4*)&C[(size_t)gr * N + gc] = o;
        }
    }
}

// ---------------------------------------------------------------------------
// Launch
// ---------------------------------------------------------------------------
extern "C" void kernel_launch(void* const* d_in, const int* in_sizes, int n_in,
                              void* d_out, int out_size)
{
    const float* x    = (const float*)d_in[0];
    const float* vec  = (const float*)d_in[1];
    const int*   ei   = (const int*)  d_in[2];
    const float* rbf  = (const float*)d_in[3];
    const float* wgt  = (const float*)d_in[4];
    const float* ev   = (const float*)d_in[5];
    const float* xw1  = (const float*)d_in[6];
    const float* xb1  = (const float*)d_in[7];
    const float* xw2  = (const float*)d_in[8];
    const float* xb2  = (const float*)d_in[9];
    const float* rw   = (const float*)d_in[10];
    const float* rb   = (const float*)d_in[11];
    const float* iw1  = (const float*)d_in[12];
    const float* ib1  = (const float*)d_in[13];
    const float* iw2  = (const float*)d_in[14];
    const float* ib2  = (const float*)d_in[15];

    const int nn = in_sizes[0] / 128;
    const int ne = in_sizes[2] / 2;

    float* out  = (float*)d_out;
    float* dx   = out;
    float* dvec = out + (size_t)nn * 128;

    float *p_h1, *p_xh, *p_m;
    __nv_bfloat16 *p_t1hi, *p_t1lo, *p_b1hi, *p_b1lo, *p_b2hi, *p_b2lo;
    cudaGetSymbolAddress((void**)&p_h1,  g_h1);
    cudaGetSymbolAddress((void**)&p_xh,  g_xh);
    cudaGetSymbolAddress((void**)&p_m,   g_m);
    cudaGetSymbolAddress((void**)&p_t1hi, g_t1hi);
    cudaGetSymbolAddress((void**)&p_t1lo, g_t1lo);
    cudaGetSymbolAddress((void**)&p_b1hi, g_b1hi);
    cudaGetSymbolAddress((void**)&p_b1lo, g_b1lo);
    cudaGetSymbolAddress((void**)&p_b2hi, g_b2hi);
    cudaGetSymbolAddress((void**)&p_b2lo, g_b2lo);

    const int SMEM4 = 7 * 16384 + 2 * 49152;   // 212992
    const int SMEM5 = 6 * 16384 + 2 * 49152;   // 196608
    cudaFuncSetAttribute((const void*)tc_gemm<0, true, 7>,
                         cudaFuncAttributeMaxDynamicSharedMemorySize, SMEM4);
    cudaFuncSetAttribute((const void*)tc_gemm<1, false, 6>,
                         cudaFuncAttributeMaxDynamicSharedMemorySize, SMEM5);

    cudaMemsetAsync(d_out, 0, (size_t)out_size * sizeof(float));

    dim3 blk(256);

    // weight-matrix conversions (tiny)
    splitT<<<(384 * 448 + 255) / 256, blk>>>(iw1, p_b1hi, p_b1lo, 416, 384, 448);
    splitT<<<(384 * 384 + 255) / 256, blk>>>(iw2, p_b2hi, p_b2lo, 384, 384, 384);

    // node projection (FFMA2)
    sgemm_bias_act<true ><<<dim3(1, (nn + BM - 1) / BM), blk>>>(x,    xw1, xb1, p_h1, nn, 128, 128);
    sgemm_bias_act<false><<<dim3(3, (nn + BM - 1) / BM), blk>>>(p_h1, xw2, xb2, p_xh, nn, 384, 128);
    // edge radial filter: g_m = rbf@rw + rb (FFMA2)
    sgemm_bias_act<false><<<dim3(3, (ne + BM - 1) / BM), blk>>>(rbf,  rw,  rb,  p_m,  ne, 384, 32);

    const int mtiles = (ne + 63) / 64;
    // gemm4: t1 = silu(wgt@iw1 + ib1) -> bf16 hi/lo planes (wgt converted in-kernel)
    tc_gemm<0, true, 7><<<mtiles, blk, SMEM4>>>(
        wgt, 416, nullptr, nullptr, p_b1hi, p_b1lo, ne, ib1,
        p_t1hi, p_t1lo,
        nullptr, nullptr, nullptr, 0, nullptr, nullptr, nullptr, nullptr);
    // gemm5 fused: w2 = t1@iw2+ib2; m = w2*rbfh*xh[src]; scatter RED into dx/dvec
    tc_gemm<1, false, 6><<<mtiles, blk, SMEM5>>>(
        nullptr, 0, p_t1hi, p_t1lo, p_b2hi, p_b2lo, ne, ib2,
        nullptr, nullptr,
        p_m, p_xh, ei, ne, vec, ev, dx, dvec);
}

// round 8
// speedup vs baseline: 1.7022x; 1.0580x over previous
#include <cuda_runtime.h>
#include <cuda_bf16.h>
#include <cstdint>

// ===========================================================================
// LEFTNet layer. One mega-kernel runs the whole edge pipeline per 64-edge CTA:
//   wgt->bf16 split (smem) -> t1=silu(wgt@iw1+ib1) (smem) -> w2=t1@iw2+ib2
//   -> rbfh=rbf@rw+rb (tensor cores, 3-pass) -> m=w2*rbfh*xh[src] -> scatter.
// Node GEMMs on FFMA2. All big GEMMs: mma.sync bf16 3-term split.
// ===========================================================================

#define NN_MAX 50000
#define NE_MAX 500000

__device__ float g_h1[(size_t)NN_MAX * 128];
__device__ float g_xh[(size_t)NN_MAX * 384];
__device__ __align__(16) __nv_bfloat16 g_b1hi[384 * 448];
__device__ __align__(16) __nv_bfloat16 g_b1lo[384 * 448];
__device__ __align__(16) __nv_bfloat16 g_b2hi[384 * 384];
__device__ __align__(16) __nv_bfloat16 g_b2lo[384 * 384];
__device__ __align__(16) __nv_bfloat16 g_rwhi[384 * 64];
__device__ __align__(16) __nv_bfloat16 g_rwlo[384 * 64];

// ---------------------------------------------------------------------------
// helpers
// ---------------------------------------------------------------------------
__device__ __forceinline__ uint32_t smem_u32(const void* p) {
    uint32_t a;
    asm("{ .reg .u64 t; cvta.to.shared.u64 t, %1; cvt.u32.u64 %0, t; }"
        : "=r"(a) : "l"(p));
    return a;
}
__device__ __forceinline__ void cp16(uint32_t s, const void* g, uint32_t nbytes) {
    asm volatile("cp.async.cg.shared.global [%0], [%1], 16, %2;"
                 :: "r"(s), "l"(g), "r"(nbytes) : "memory");
}
__device__ __forceinline__ void cp_commit() { asm volatile("cp.async.commit_group;" ::: "memory"); }
__device__ __forceinline__ void cp_wait1()  { asm volatile("cp.async.wait_group 1;" ::: "memory"); }
__device__ __forceinline__ void cp_wait0()  { asm volatile("cp.async.wait_group 0;" ::: "memory"); }

__device__ __forceinline__ uint32_t swz(uint32_t off) { return off ^ ((off >> 3) & 0x70); }

__device__ __forceinline__ void ldm_x4(uint32_t& r0, uint32_t& r1, uint32_t& r2, uint32_t& r3,
                                       uint32_t addr) {
    asm volatile("ldmatrix.sync.aligned.m8n8.x4.shared.b16 {%0, %1, %2, %3}, [%4];"
                 : "=r"(r0), "=r"(r1), "=r"(r2), "=r"(r3) : "r"(addr));
}
__device__ __forceinline__ void mma_bf16(float* c, const uint32_t* a, const uint32_t* b) {
    asm volatile("mma.sync.aligned.m16n8k16.row.col.f32.bf16.bf16.f32 "
                 "{%0, %1, %2, %3}, {%4, %5, %6, %7}, {%8, %9}, {%0, %1, %2, %3};"
                 : "+f"(c[0]), "+f"(c[1]), "+f"(c[2]), "+f"(c[3])
                 : "r"(a[0]), "r"(a[1]), "r"(a[2]), "r"(a[3]), "r"(b[0]), "r"(b[1]));
}
__device__ __forceinline__ void red_add_v4(float* p, float4 v) {
    asm volatile("red.global.add.v4.f32 [%0], {%1, %2, %3, %4};"
                 :: "l"(p), "f"(v.x), "f"(v.y), "f"(v.z), "f"(v.w) : "memory");
}
__device__ __forceinline__ float silu_f(float v) {
    return v * (1.0f / (1.0f + __expf(-v)));
}
__device__ __forceinline__ void split_bf16(float v, __nv_bfloat16& h, __nv_bfloat16& l) {
    h = __float2bfloat16(v);
    l = __float2bfloat16(v - __bfloat162float(h));
}

// smem region layout (bytes from A0):
//   phase1 A: wgt hi [0,57344) + lo [57344,114688)            (7 chunks each)
//   phase2 A: t1  hi [0,49152) + lo [49152,98304)             (6 chunks each)
//   rbf planes:    hi [99328,107520) + lo [107520,115712)
//   m_st staging:  [0, 99328)  (64 x 388 fp32)
//   B region:      [116736, 116736+98304)  two 48KB buffers
#define AREG   116736
#define RBF_HI 99328
#define RBF_LO 107520
#define MEGA_SMEM (116736 + 98304)

__global__ __launch_bounds__(256)
void mega_kernel(const float* __restrict__ wgt,
                 const __nv_bfloat16* __restrict__ B1hi, const __nv_bfloat16* __restrict__ B1lo,
                 const __nv_bfloat16* __restrict__ B2hi, const __nv_bfloat16* __restrict__ B2lo,
                 const __nv_bfloat16* __restrict__ RWhi, const __nv_bfloat16* __restrict__ RWlo,
                 const float* __restrict__ rbf,
                 const float* __restrict__ ib1, const float* __restrict__ ib2,
                 const float* __restrict__ rb,
                 const float* __restrict__ xh,
                 const int* __restrict__ ei, int E,
                 const float* __restrict__ vec, const float* __restrict__ ev,
                 float* __restrict__ dx, float* __restrict__ dvec)
{
    extern __shared__ char dsm[];
    const uint32_t A0 = smem_u32(dsm);
    const uint32_t B0 = A0 + AREG;
    float* m_st = (float*)dsm;                    // stride 388

    const int tid  = threadIdx.x;
    const int wid  = tid >> 5;
    const int lane = tid & 31;
    const int row0 = blockIdx.x * 64;

    const int wm = (wid >> 2) * 32;
    const int wn = (wid & 3) * 96;
    const int g   = lane >> 2;
    const int tig = lane & 3;
    const int a_r = (lane & 7) + ((lane & 8) ? 8 : 0);
    const int a_c = lane >> 4;
    const int b_r = (lane & 7) + ((lane & 16) ? 8 : 0);
    const int b_c = (lane >> 3) & 1;

    float acc[2][12][4];
#pragma unroll
    for (int i = 0; i < 2; i++)
#pragma unroll
        for (int j = 0; j < 12; j++)
#pragma unroll
            for (int k = 0; k < 4; k++) acc[i][j][k] = 0.0f;

    int bufc = 0;
    auto loadB = [&](const __nv_bfloat16* Bp, int k0, int KPb) {
        const uint32_t Bb = B0 + (bufc & 1) * 49152;
#pragma unroll
        for (int i = 0; i < 12; i++) {
            int id = tid + i * 256;
            int r  = id >> 3, c16 = id & 7;
            cp16(Bb + swz(r * 128 + c16 * 16),
                 Bp + (size_t)r * KPb + k0 + c16 * 8, 16u);
        }
        cp_commit();
        bufc++;
    };

    auto mma_chunk = [&](uint32_t Ab, uint32_t Bb) {
#pragma unroll
        for (int ks = 0; ks < 4; ks++) {
            const int cbase = ks * 2;
            uint32_t af[2][4], bf[12][2];
#pragma unroll
            for (int mt = 0; mt < 2; mt++) {
                int r = wm + mt * 16 + a_r;
                ldm_x4(af[mt][0], af[mt][1], af[mt][2], af[mt][3],
                       Ab + swz(r * 128 + (cbase + a_c) * 16));
            }
#pragma unroll
            for (int np = 0; np < 6; np++) {
                int r = wn + np * 16 + b_r;
                uint32_t r0, r1, r2, r3;
                ldm_x4(r0, r1, r2, r3, Bb + swz(r * 128 + (cbase + b_c) * 16));
                bf[np * 2 + 0][0] = r0; bf[np * 2 + 0][1] = r1;
                bf[np * 2 + 1][0] = r2; bf[np * 2 + 1][1] = r3;
            }
#pragma unroll
            for (int mt = 0; mt < 2; mt++)
#pragma unroll
                for (int nt = 0; nt < 12; nt++)
                    mma_bf16(acc[mt][nt], af[mt], bf[nt]);
        }
    };

    // run 3 passes over chunks; assumes chunk0 already prefetched.
    auto run_main = [&](int NCHv, const __nv_bfloat16* Bhi, const __nv_bfloat16* Blo,
                        int KPb, uint32_t aHi, uint32_t aLo) {
        const int total = 3 * NCHv;
        const int b0 = bufc - 1;
        for (int c = 0; c < total; c++) {
            if (c + 1 < total) {
                int nc = c + 1, pass = nc / NCHv;
                loadB(pass == 2 ? Blo : Bhi, (nc - pass * NCHv) << 6, KPb);
                cp_wait1();
            } else cp_wait0();
            __syncthreads();
            int pass = c / NCHv, kch = c - pass * NCHv;
            mma_chunk((pass == 1 ? aLo : aHi) + kch * 8192,
                      B0 + ((b0 + c) & 1) * 49152);
            __syncthreads();
        }
    };

    // ================= phase 1: wgt conversion + mainloop1 =================
    loadB(B1hi, 0, 448);
    {
#pragma unroll
        for (int i = 0; i < 28; i++) {            // 64 rows x 112 f4-groups
            int id   = tid + i * 256;
            int r    = id / 112;
            int gcol = (id - r * 112) * 4;
            int gr   = row0 + r;
            float4 v = make_float4(0.f, 0.f, 0.f, 0.f);
            if (gr < E && gcol < 416)
                v = *(const float4*)&wgt[(size_t)gr * 416 + gcol];
            float a[4] = {v.x, v.y, v.z, v.w};
            unsigned long long hpk = 0ull, lpk = 0ull;
#pragma unroll
            for (int q = 0; q < 4; q++) {
                __nv_bfloat16 h, l; split_bf16(a[q], h, l);
                hpk |= (unsigned long long)__bfloat16_as_ushort(h) << (16 * q);
                lpk |= (unsigned long long)__bfloat16_as_ushort(l) << (16 * q);
            }
            int ch = gcol >> 6, cc = gcol & 63;
            uint32_t off = ch * 8192 + swz(r * 128 + cc * 2);
            *(unsigned long long*)(dsm + off)          = hpk;
            *(unsigned long long*)(dsm + 57344 + off)  = lpk;
        }
    }
    run_main(7, B1hi, B1lo, 448, A0, A0 + 57344);

    // ============ phase 2: t1 = silu(acc+ib1) -> smem; rbf -> smem ==========
    loadB(B2hi, 0, 384);                          // prefetch mainloop2 chunk0
#pragma unroll
    for (int mt = 0; mt < 2; mt++)
#pragma unroll
        for (int half = 0; half < 2; half++) {
            const int er = wm + mt * 16 + g + half * 8;
#pragma unroll
            for (int nt = 0; nt < 12; nt++) {
                const int col = wn + nt * 8 + tig * 2;
                float s0 = silu_f(acc[mt][nt][half * 2 + 0] + ib1[col]);
                float s1 = silu_f(acc[mt][nt][half * 2 + 1] + ib1[col + 1]);
                __nv_bfloat16 h0, l0, h1, l1;
                split_bf16(s0, h0, l0);
                split_bf16(s1, h1, l1);
                int ch = col >> 6, cc = col & 63;
                uint32_t off = ch * 8192 + swz(er * 128 + cc * 2);
                *(uint32_t*)(dsm + off) =
                    (uint32_t)__bfloat16_as_ushort(h0) |
                    ((uint32_t)__bfloat16_as_ushort(h1) << 16);
                *(uint32_t*)(dsm + 49152 + off) =
                    (uint32_t)__bfloat16_as_ushort(l0) |
                    ((uint32_t)__bfloat16_as_ushort(l1) << 16);
            }
        }
    // rbf tile -> hi/lo planes (64 x 64, cols 32.. zero)
#pragma unroll
    for (int i = 0; i < 4; i++) {
        int id = tid + i * 256;                   // 64 rows x 16 u64 groups
        int r  = id >> 4, g4 = id & 15;
        int c4 = g4 * 4;
        int gr = row0 + r;
        float4 v = make_float4(0.f, 0.f, 0.f, 0.f);
        if (gr < E && c4 < 32)
            v = *(const float4*)&rbf[(size_t)gr * 32 + c4];
        float a[4] = {v.x, v.y, v.z, v.w};
        unsigned long long hpk = 0ull, lpk = 0ull;
#pragma unroll
        for (int q = 0; q < 4; q++) {
            __nv_bfloat16 h, l; split_bf16(a[q], h, l);
            hpk |= (unsigned long long)__bfloat16_as_ushort(h) << (16 * q);
            lpk |= (unsigned long long)__bfloat16_as_ushort(l) << (16 * q);
        }
        uint32_t off = swz(r * 128 + g4 * 8);
        *(unsigned long long*)(dsm + RBF_HI + off) = hpk;
        *(unsigned long long*)(dsm + RBF_LO + off) = lpk;
    }
#pragma unroll
    for (int i = 0; i < 2; i++)
#pragma unroll
        for (int j = 0; j < 12; j++)
#pragma unroll
            for (int k = 0; k < 4; k++) acc[i][j][k] = 0.0f;
    run_main(6, B2hi, B2lo, 384, A0, A0 + 49152);

    // ====== phase 3: stage w2+ib2 -> m_st; rbfh via tensor cores ===========
    loadB(RWhi, 0, 64);                           // prefetch rbfh chunk0
#pragma unroll
    for (int mt = 0; mt < 2; mt++)
#pragma unroll
        for (int half = 0; half < 2; half++) {
            const int er = wm + mt * 16 + g + half * 8;
#pragma unroll
            for (int nt = 0; nt < 12; nt++) {
                const int col = wn + nt * 8 + tig * 2;
                float2 o;
                o.x = acc[mt][nt][half * 2 + 0] + ib2[col];
                o.y = acc[mt][nt][half * 2 + 1] + ib2[col + 1];
                *(float2*)&m_st[er * 388 + col] = o;
            }
        }
#pragma unroll
    for (int i = 0; i < 2; i++)
#pragma unroll
        for (int j = 0; j < 12; j++)
#pragma unroll
            for (int k = 0; k < 4; k++) acc[i][j][k] = 0.0f;
    run_main(1, RWhi, RWlo, 64, A0 + RBF_HI, A0 + RBF_LO);

    // multiply own cells: m_st *= (rbfh + rb)
#pragma unroll
    for (int mt = 0; mt < 2; mt++)
#pragma unroll
        for (int half = 0; half < 2; half++) {
            const int er = wm + mt * 16 + g + half * 8;
#pragma unroll
            for (int nt = 0; nt < 12; nt++) {
                const int col = wn + nt * 8 + tig * 2;
                float2 o = *(float2*)&m_st[er * 388 + col];
                o.x *= acc[mt][nt][half * 2 + 0] + rb[col];
                o.y *= acc[mt][nt][half * 2 + 1] + rb[col + 1];
                *(float2*)&m_st[er * 388 + col] = o;
            }
        }
    __syncthreads();

    // ==================== phase 4: warp-per-edge scatter ===================
    const float is3 = 0.57735026918962576f;       // 1/sqrt(3)
    const float ish = 0.08838834764831845f;       // 1/sqrt(128)
#pragma unroll
    for (int i = 0; i < 8; i++) {
        const int er = wid * 8 + i;
        const int e  = row0 + er;
        if (e >= E) continue;
        const int s = ei[e];
        const int d = ei[E + e];

        const float* st = m_st + er * 388;
        float4 a0 = *(const float4*)&st[lane * 4];
        float4 a1 = *(const float4*)&st[128 + lane * 4];
        float4 a2 = *(const float4*)&st[256 + lane * 4];

        const float* xr = xh + (size_t)s * 384;
        float4 x0 = *(const float4*)&xr[lane * 4];
        float4 x1 = *(const float4*)&xr[128 + lane * 4];
        float4 x2 = *(const float4*)&xr[256 + lane * 4];

        float4 xm, h2, h3;
        xm.x = a0.x * x0.x;  xm.y = a0.y * x0.y;
        xm.z = a0.z * x0.z;  xm.w = a0.w * x0.w;
        h2.x = a1.x * x1.x * is3;  h2.y = a1.y * x1.y * is3;
        h2.z = a1.z * x1.z * is3;  h2.w = a1.w * x1.w * is3;
        h3.x = a2.x * x2.x;  h3.y = a2.y * x2.y;
        h3.z = a2.z * x2.z;  h3.w = a2.w * x2.w;

        red_add_v4(dx + (size_t)d * 128 + lane * 4, xm);

        float evd[3];
        evd[0] = __ldg(&ev[(size_t)e * 3 + 0]);
        evd[1] = __ldg(&ev[(size_t)e * 3 + 1]);
        evd[2] = __ldg(&ev[(size_t)e * 3 + 2]);
        const float4* v4 = (const float4*)(vec + (size_t)s * 384);
#pragma unroll
        for (int t = 0; t < 3; t++) {
            float4 v = v4[t * 32 + lane];
            float4 o;
            o.x = (v.x * h2.x + h3.x * evd[t]) * ish;
            o.y = (v.y * h2.y + h3.y * evd[t]) * ish;
            o.z = (v.z * h2.z + h3.z * evd[t]) * ish;
            o.w = (v.w * h2.w + h3.w * evd[t]) * ish;
            red_add_v4(dvec + ((size_t)d * 3 + t) * 128 + lane * 4, o);
        }
    }
}

// ---------------------------------------------------------------------------
// Transpose+split weights: src [K,N] fp32 -> hi/lo [N,KP] bf16
// ---------------------------------------------------------------------------
__global__ void splitT(const float* __restrict__ src,
                       __nv_bfloat16* __restrict__ hi,
                       __nv_bfloat16* __restrict__ lo,
                       int K, int N, int KP)
{
    int t = blockIdx.x * blockDim.x + threadIdx.x;
    if (t >= N * KP) return;
    int n = t / KP, k = t - n * KP;
    float v = (k < K) ? src[(size_t)k * N + n] : 0.0f;
    __nv_bfloat16 h, l;
    h = __float2bfloat16(v);
    l = __float2bfloat16(v - __bfloat162float(h));
    hi[t] = h;
    lo[t] = l;
}

// ---------------------------------------------------------------------------
// FFMA2 SGEMM for the node GEMMs
// ---------------------------------------------------------------------------
#define BM 128
#define BN 128
#define BK 16

__device__ __forceinline__ unsigned long long pack2(float lo, float hi) {
    unsigned long long r;
    asm("mov.b64 %0, {%1, %2};" : "=l"(r) : "f"(lo), "f"(hi));
    return r;
}
__device__ __forceinline__ void unpack2(unsigned long long v, float& lo, float& hi) {
    asm("mov.b64 {%0, %1}, %2;" : "=f"(lo), "=f"(hi) : "l"(v));
}
__device__ __forceinline__ void ffma2(unsigned long long& d,
                                      unsigned long long a, unsigned long long b) {
    asm("fma.rn.f32x2 %0, %1, %2, %0;" : "+l"(d) : "l"(a), "l"(b));
}

template<bool SILU>
__global__ __launch_bounds__(256, 2)
void sgemm_bias_act(const float* __restrict__ A, const float* __restrict__ B,
                    const float* __restrict__ bias, float* __restrict__ C,
                    int M, int N, int K)
{
    __shared__ float As[BK][BM + 4];
    __shared__ float Bs[BK][BN];

    const int tid  = threadIdx.x;
    const int tx   = tid & 15;
    const int ty   = tid >> 4;
    const int row0 = blockIdx.y * BM;
    const int col0 = blockIdx.x * BN;

    unsigned long long acc2[8][4];
#pragma unroll
    for (int i = 0; i < 8; i++)
#pragma unroll
        for (int j = 0; j < 4; j++) acc2[i][j] = 0ull;

    const int a_row = tid >> 2;
    const int a_seg = tid & 3;
    const int b_kk  = tid >> 5;
    const int b_c4  = (tid & 31) << 2;

    for (int k0 = 0; k0 < K; k0 += BK) {
#pragma unroll
        for (int it = 0; it < 2; it++) {
            int r  = a_row + it * 64;
            int gr = row0 + r;
            float4 v = make_float4(0.f, 0.f, 0.f, 0.f);
            if (gr < M)
                v = *(const float4*)&A[(size_t)gr * K + k0 + a_seg * 4];
            As[a_seg * 4 + 0][r] = v.x;
            As[a_seg * 4 + 1][r] = v.y;
            As[a_seg * 4 + 2][r] = v.z;
            As[a_seg * 4 + 3][r] = v.w;
        }
#pragma unroll
        for (int it = 0; it < 2; it++) {
            int kk = b_kk + it * 8;
            *(float4*)&Bs[kk][b_c4] =
                *(const float4*)&B[(size_t)(k0 + kk) * N + col0 + b_c4];
        }
        __syncthreads();

#pragma unroll
        for (int kk = 0; kk < BK; kk++) {
            float4 a0 = *(const float4*)&As[kk][ty * 4];
            float4 a1 = *(const float4*)&As[kk][64 + ty * 4];
            float4 b0 = *(const float4*)&Bs[kk][tx * 4];
            float4 b1 = *(const float4*)&Bs[kk][64 + tx * 4];
            unsigned long long bp[4] = {
                pack2(b0.x, b0.y), pack2(b0.z, b0.w),
                pack2(b1.x, b1.y), pack2(b1.z, b1.w)
            };
            float av[8] = {a0.x, a0.y, a0.z, a0.w, a1.x, a1.y, a1.z, a1.w};
#pragma unroll
            for (int i = 0; i < 8; i++) {
                unsigned long long ap = pack2(av[i], av[i]);
#pragma unroll
                for (int jp = 0; jp < 4; jp++)
                    ffma2(acc2[i][jp], ap, bp[jp]);
            }
        }
        __syncthreads();
    }

#pragma unroll
    for (int i = 0; i < 8; i++) {
        int r  = (i < 4) ? (ty * 4 + i) : (64 + ty * 4 + (i - 4));
        int gr = row0 + r;
        if (gr >= M) continue;
#pragma unroll
        for (int jg = 0; jg < 2; jg++) {
            int c  = (jg == 0) ? (tx * 4) : (64 + tx * 4);
            int gc = col0 + c;
            float4 bi = *(const float4*)&bias[gc];
            float4 o;
            unpack2(acc2[i][jg * 2 + 0], o.x, o.y);
            unpack2(acc2[i][jg * 2 + 1], o.z, o.w);
            o.x += bi.x; o.y += bi.y; o.z += bi.z; o.w += bi.w;
            if (SILU) {
                o.x = silu_f(o.x); o.y = silu_f(o.y);
                o.z = silu_f(o.z); o.w = silu_f(o.w);
            }
            *(float4*)&C[(size_t)gr * N + gc] = o;
        }
    }
}

// ---------------------------------------------------------------------------
// Launch
// ---------------------------------------------------------------------------
extern "C" void kernel_launch(void* const* d_in, const int* in_sizes, int n_in,
                              void* d_out, int out_size)
{
    const float* x    = (const float*)d_in[0];
    const float* vec  = (const float*)d_in[1];
    const int*   ei   = (const int*)  d_in[2];
    const float* rbf  = (const float*)d_in[3];
    const float* wgt  = (const float*)d_in[4];
    const float* ev   = (const float*)d_in[5];
    const float* xw1  = (const float*)d_in[6];
    const float* xb1  = (const float*)d_in[7];
    const float* xw2  = (const float*)d_in[8];
    const float* xb2  = (const float*)d_in[9];
    const float* rw   = (const float*)d_in[10];
    const float* rb   = (const float*)d_in[11];
    const float* iw1  = (const float*)d_in[12];
    const float* ib1  = (const float*)d_in[13];
    const float* iw2  = (const float*)d_in[14];
    const float* ib2  = (const float*)d_in[15];

    const int nn = in_sizes[0] / 128;
    const int ne = in_sizes[2] / 2;

    float* out  = (float*)d_out;
    float* dx   = out;
    float* dvec = out + (size_t)nn * 128;

    float *p_h1, *p_xh;
    __nv_bfloat16 *p_b1hi, *p_b1lo, *p_b2hi, *p_b2lo, *p_rwhi, *p_rwlo;
    cudaGetSymbolAddress((void**)&p_h1,  g_h1);
    cudaGetSymbolAddress((void**)&p_xh,  g_xh);
    cudaGetSymbolAddress((void**)&p_b1hi, g_b1hi);
    cudaGetSymbolAddress((void**)&p_b1lo, g_b1lo);
    cudaGetSymbolAddress((void**)&p_b2hi, g_b2hi);
    cudaGetSymbolAddress((void**)&p_b2lo, g_b2lo);
    cudaGetSymbolAddress((void**)&p_rwhi, g_rwhi);
    cudaGetSymbolAddress((void**)&p_rwlo, g_rwlo);

    cudaFuncSetAttribute(mega_kernel,
                         cudaFuncAttributeMaxDynamicSharedMemorySize, MEGA_SMEM);

    cudaMemsetAsync(d_out, 0, (size_t)out_size * sizeof(float));

    dim3 blk(256);

    // weight conversions (tiny)
    splitT<<<(384 * 448 + 255) / 256, blk>>>(iw1, p_b1hi, p_b1lo, 416, 384, 448);
    splitT<<<(384 * 384 + 255) / 256, blk>>>(iw2, p_b2hi, p_b2lo, 384, 384, 384);
    splitT<<<(384 * 64  + 255) / 256, blk>>>(rw,  p_rwhi, p_rwlo, 32,  384, 64);

    // node projection (FFMA2): xh = silu(x@xw1+xb1)@xw2+xb2
    sgemm_bias_act<true ><<<dim3(1, (nn + BM - 1) / BM), blk>>>(x,    xw1, xb1, p_h1, nn, 128, 128);
    sgemm_bias_act<false><<<dim3(3, (nn + BM - 1) / BM), blk>>>(p_h1, xw2, xb2, p_xh, nn, 384, 128);

    // mega kernel: whole edge pipeline
    const int mtiles = (ne + 63) / 64;
    mega_kernel<<<mtiles, blk, MEGA_SMEM>>>(
        wgt, p_b1hi, p_b1lo, p_b2hi, p_b2lo, p_rwhi, p_rwlo,
        rbf, ib1, ib2, rb, p_xh, ei, ne, vec, ev, dx, dvec);
}